// round 12
// baseline (speedup 1.0000x reference)
#include <cuda_runtime.h>
#include <cuda_fp16.h>
#include <cstdint>

// ---------------- problem constants ----------------
#define NB  16
#define HN  8
#define HDM 32
#define DM  256
#define GP  512
#define GD  128
#define NHS 128          // NB*HN slices
#define SEG 16
// (1/sqrt(32)) * log2(e)
#define EXPSC 0.2550526808750678f

// swizzled smem index: conflict-free for sink strip pattern
#define SIDX(c) ((((c) & 31) * 17) + ((c) >> 5))

// mega-kernel shared memory layout (bytes)
#define ESTR   520                       // halfs per E row (1040B: +4 banks/row)
#define SM_E   0                         // 128*520*2 = 133120
#define SM_QK  133120                    // Qs 32*137*4 =17536 ; Ks +17536 (strips alias)
#define SM_MR  168192                    // float[128]
#define SM_MC  168704                    // float[512]
#define SM_TOT 170752

// ---------------- scratch (static device globals; no runtime alloc) ------------
__device__ float  g_mp[NB*GP];
__device__ float  g_md[NB*GD];
__device__ float  g_part[2*NB*SEG*DM];
__device__ float  g_cpart[2*NB*SEG];
__device__ float  g_kp[NHS*GP*HDM];
__device__ float  g_qd[NHS*GD*HDM];
__device__ __half g_E [NHS*GD*GP];
__device__ float  g_r [NHS*GD];
__device__ float  g_c [NHS*GP];
__device__ int    g_maskmode;

// ---------------- tf32 + mma + ex2 helpers ---------------------------------------
__device__ __forceinline__ uint32_t tf32cvt(float x) {
    uint32_t r;
    asm("cvt.rna.tf32.f32 %0, %1;" : "=r"(r) : "f"(x));
    return r;
}
__device__ __forceinline__ void mma_tf32(float& c0, float& c1, float& c2, float& c3,
                                         uint32_t a0, uint32_t a1, uint32_t a2, uint32_t a3,
                                         uint32_t b0, uint32_t b1) {
    asm volatile(
        "mma.sync.aligned.m16n8k8.row.col.f32.tf32.tf32.f32 "
        "{%0,%1,%2,%3}, {%4,%5,%6,%7}, {%8,%9}, {%0,%1,%2,%3};"
        : "+f"(c0), "+f"(c1), "+f"(c2), "+f"(c3)
        : "r"(a0), "r"(a1), "r"(a2), "r"(a3), "r"(b0), "r"(b1));
}
__device__ __forceinline__ uint32_t ex2_f16x2(uint32_t x) {
    uint32_t r;
    asm("ex2.approx.f16x2 %0, %1;" : "=r"(r) : "r"(x));
    return r;
}

// ---------------- mask dtype probe ------------------------------------------------
__global__ void k_probe(const unsigned int* __restrict__ m) {
    __shared__ int cnt[4];
    int t = threadIdx.x;
    if (t < 4) cnt[t] = 0;
    __syncthreads();
    unsigned w = m[t];
    if (w == 0x3F803F80u || w == 0x3C003C00u) atomicAdd(&cnt[0], 1);
    if (w == 0x3F800000u)                     atomicAdd(&cnt[1], 1);
    if (w > 1u)                               atomicAdd(&cnt[2], 1);
    __syncthreads();
    if (t == 0) {
        int mode;
        if (cnt[0] >= 4)      mode = 3;
        else if (cnt[1] >= 4) mode = 0;
        else if (cnt[2] > 0)  mode = 2;
        else                  mode = 1;
        g_maskmode = mode;
    }
}

__device__ __forceinline__ float mask_at(const void* M, int tok, int mode) {
    switch (mode) {
        case 0:  return ((const float*)M)[tok] != 0.0f ? 1.0f : 0.0f;
        case 1:  return ((const int*)M)[tok]   != 0    ? 1.0f : 0.0f;
        case 2:  return ((const unsigned char*)M)[tok] ? 1.0f : 0.0f;
        default: return ((const unsigned short*)M)[tok] ? 1.0f : 0.0f;
    }
}

// ---------------- fused launch 1: inline-grouped masked sums + proj GEMM ----------
// blocks [0,512): msum (raw tokens, inline group masks); [512,768): proj.
#define ASTR 137
__global__ __launch_bounds__(256) void k_fuse1(const float* __restrict__ P,
                                               const float* __restrict__ Dr,
                                               const void* __restrict__ MP,
                                               const void* __restrict__ MD,
                                               const float* __restrict__ Wkp,
                                               const float* __restrict__ Wqd) {
    int tid = threadIdx.x;
    if (blockIdx.x < 512) {
        // ---- masked sums over raw tokens + group masks ----
        __shared__ float sm_m[32];
        int s = blockIdx.x;
        int n = s & 15, ent = (s >> 4) & 1, seg = s >> 5;
        const float* X = ent ? Dr : P;
        const void*  M = ent ? MD : MP;
        int G = ent ? GD : GP;
        int chunk = G / SEG;                 // 32 (prot) or 8 (drug)
        int gb = n*G + seg*chunk;            // first global group index
        int mode = g_maskmode;
        if (tid < chunk) {
            int gi = gb + tid;
            float mm = mask_at(M, 4*gi+0, mode) + mask_at(M, 4*gi+1, mode)
                     + mask_at(M, 4*gi+2, mode) + mask_at(M, 4*gi+3, mode);
            float mv = (mm > 0.0f) ? 1.0f : 0.0f;
            sm_m[tid] = mv;
            (ent ? g_md : g_mp)[gi] = mv;
        }
        __syncthreads();
        int d = tid;
        float a0 = 0.f, a1 = 0.f, a2 = 0.f, a3 = 0.f;
        for (int g = 0; g < chunk; g += 4) {
            size_t t0 = (size_t)(4*(gb + g)) * DM + d;
            a0 += sm_m[g+0] * (X[t0        ] + X[t0 + DM  ] + X[t0 + 2*DM ] + X[t0 + 3*DM ]);
            a1 += sm_m[g+1] * (X[t0 + 4*DM ] + X[t0 + 5*DM ] + X[t0 + 6*DM ] + X[t0 + 7*DM ]);
            a2 += sm_m[g+2] * (X[t0 + 8*DM ] + X[t0 + 9*DM ] + X[t0 + 10*DM] + X[t0 + 11*DM]);
            a3 += sm_m[g+3] * (X[t0 + 12*DM] + X[t0 + 13*DM] + X[t0 + 14*DM] + X[t0 + 15*DM]);
        }
        g_part[((ent*NB + n)*SEG + seg)*DM + d] = 0.25f * ((a0 + a1) + (a2 + a3));
        if (d == 0) {
            float c = 0.0f;
            for (int g = 0; g < chunk; g++) c += sm_m[g];
            g_cpart[(ent*NB + n)*SEG + seg] = c;
        }
        return;
    }
    // ---- projection GEMM: single TF32, CTA 128x128, K-step 32, on-the-fly grouping
    int pb = blockIdx.x - 512;
    int bx = pb & 63, by = (pb >> 6) & 1, bz = pb >> 7;
    const float* Xt; const float* W; float* OUT; int L;
    if (bz == 0) { Xt = P;  W = Wkp; OUT = g_kp; L = GP; }
    else         { if (bx >= 16) return;
                   Xt = Dr; W = Wqd; OUT = g_qd; L = GD; }
    __shared__ uint32_t AsH[32*ASTR];
    __shared__ uint32_t BsH[32*ASTR];

    int lane = tid & 31, w = tid >> 5;
    int g = lane >> 2, tk = lane & 3;
    int wm = (w & 3) * 32, wn = (w >> 2) * 64;
    int m0 = bx * 128, o0 = by * 128;

    float c[2][8][4];
#pragma unroll
    for (int mi = 0; mi < 2; mi++)
#pragma unroll
        for (int ni = 0; ni < 8; ni++)
#pragma unroll
            for (int r = 0; r < 4; r++) c[mi][ni][r] = 0.0f;

    for (int k0 = 0; k0 < 256; k0 += 32) {
#pragma unroll
        for (int s = 0; s < 4; s++) {
            int f = tid + s*256;
            int row = f >> 3, c4 = f & 7;
            // A row = group (m0+row): mean of 4 token rows (independent LDGs)
            size_t tb = (size_t)(4*(m0+row)) * 256 + k0 + c4*4;
            float4 x0 = *(const float4*)&Xt[tb        ];
            float4 x1 = *(const float4*)&Xt[tb + 256  ];
            float4 x2 = *(const float4*)&Xt[tb + 512  ];
            float4 x3 = *(const float4*)&Xt[tb + 768  ];
            AsH[(c4*4+0)*ASTR + row] = tf32cvt(0.25f*((x0.x+x1.x)+(x2.x+x3.x)));
            AsH[(c4*4+1)*ASTR + row] = tf32cvt(0.25f*((x0.y+x1.y)+(x2.y+x3.y)));
            AsH[(c4*4+2)*ASTR + row] = tf32cvt(0.25f*((x0.z+x1.z)+(x2.z+x3.z)));
            AsH[(c4*4+3)*ASTR + row] = tf32cvt(0.25f*((x0.w+x1.w)+(x2.w+x3.w)));
            float4 vb = *(const float4*)&W[(size_t)(o0+row)*256 + k0 + c4*4];
            BsH[(c4*4+0)*ASTR + row] = tf32cvt(vb.x);
            BsH[(c4*4+1)*ASTR + row] = tf32cvt(vb.y);
            BsH[(c4*4+2)*ASTR + row] = tf32cvt(vb.z);
            BsH[(c4*4+3)*ASTR + row] = tf32cvt(vb.w);
        }
        __syncthreads();
#pragma unroll
        for (int kh = 0; kh < 4; kh++) {
            int kb = kh*8;
            uint32_t aH[2][4];
#pragma unroll
            for (int mi = 0; mi < 2; mi++) {
                int rb = wm + mi*16 + g;
                aH[mi][0] = AsH[(kb+tk  )*ASTR + rb];
                aH[mi][1] = AsH[(kb+tk  )*ASTR + rb + 8];
                aH[mi][2] = AsH[(kb+tk+4)*ASTR + rb];
                aH[mi][3] = AsH[(kb+tk+4)*ASTR + rb + 8];
            }
            uint32_t bH[8][2];
#pragma unroll
            for (int ni = 0; ni < 8; ni++) {
                int nb = wn + ni*8 + g;
                bH[ni][0] = BsH[(kb+tk  )*ASTR + nb];
                bH[ni][1] = BsH[(kb+tk+4)*ASTR + nb];
            }
#pragma unroll
            for (int mi = 0; mi < 2; mi++)
#pragma unroll
                for (int ni = 0; ni < 8; ni++) {
                    float* cc = c[mi][ni];
                    mma_tf32(cc[0],cc[1],cc[2],cc[3],
                             aH[mi][0],aH[mi][1],aH[mi][2],aH[mi][3],
                             bH[ni][0],bH[ni][1]);
                }
        }
        __syncthreads();
    }

#pragma unroll
    for (int mi = 0; mi < 2; mi++)
#pragma unroll
        for (int ni = 0; ni < 8; ni++) {
            int o = o0 + wn + ni*8 + 2*tk;
            int h = o >> 5, dd = o & 31;
            int m = m0 + wm + mi*16 + g;
            int nb = m / L, gg = m % L;
            float* dst = &OUT[(((size_t)(nb*HN + h))*L + gg)*HDM + dd];
            *(float2*)dst = make_float2(c[mi][ni][0], c[mi][ni][1]);
            int m2 = m + 8;
            int nb2 = m2 / L, gg2 = m2 % L;
            float* dst2 = &OUT[(((size_t)(nb2*HN + h))*L + gg2)*HDM + dd];
            *(float2*)dst2 = make_float2(c[mi][ni][2], c[mi][ni][3]);
        }
}

// ---------------- mega kernel: logits (TF32 MMA) + 4x Sinkhorn, E in smem ---------
// blocks [0,128): one slice each, 512 threads; blocks [128,144): vembed.
__global__ __launch_bounds__(512) void k_mega(const float* __restrict__ Wvp,
                                              const float* __restrict__ Wvd,
                                              float* __restrict__ qout, int do_q) {
    extern __shared__ char smem[];
    int tid = threadIdx.x;
    int lane = tid & 31, w = tid >> 5;

    if (blockIdx.x >= NHS) {
        if (!do_q) return;
        float* sp   = (float*)smem;
        float* sd   = sp + DM;
        float* cnts = sd + DM;
        int n = blockIdx.x - NHS;
        if (tid < DM) {
            float accp = 0.0f, accd = 0.0f;
#pragma unroll
            for (int s = 0; s < SEG; s++) {
                accp += g_part[((0*NB + n)*SEG + s)*DM + tid];
                accd += g_part[((1*NB + n)*SEG + s)*DM + tid];
            }
            sp[tid] = accp; sd[tid] = accd;
        }
        if (tid < 2) {
            float c = 0.0f;
#pragma unroll
            for (int s = 0; s < SEG; s++) c += g_cpart[(tid*NB + n)*SEG + s];
            cnts[tid] = c;
        }
        __syncthreads();
        float cp = cnts[0], cd = cnts[1];
        for (int o = w; o < DM; o += 16) {
            float acc = 0.0f;
#pragma unroll
            for (int t = 0; t < 8; t++) {
                int k = lane + t*32;
                acc += sp[k]*Wvp[(size_t)o*DM + k] + sd[k]*Wvd[(size_t)o*DM + k];
            }
#pragma unroll
            for (int off = 16; off > 0; off >>= 1)
                acc += __shfl_xor_sync(0xFFFFFFFFu, acc, off);
            if (lane == 0) {
                qout[(size_t)n*512 + o]       = 0.5f * acc / cp;
                qout[(size_t)n*512 + 256 + o] = 0.5f * acc / cd;
            }
        }
        return;
    }

    // ---- per-slice logits + Sinkhorn ----
    int slice = blockIdx.x;
    int n = slice >> 3;
    const float* q = g_qd + (size_t)slice * GD * HDM;
    const float* k = g_kp + (size_t)slice * GP * HDM;

    __half*   Esm   = (__half*)(smem + SM_E);
    uint32_t* Qs    = (uint32_t*)(smem + SM_QK);
    uint32_t* Ks    = Qs + 32*ASTR;
    float*    strip = (float*)(smem + SM_QK);
    float*    mr    = (float*)(smem + SM_MR);
    float*    mc    = (float*)(smem + SM_MC);

    int g = lane >> 2, tk = lane & 3;
    int wm = (w & 3) * 32, wn = (w >> 2) * 32;

#pragma unroll
    for (int s = 0; s < 2; s++) {
        int f = tid + s*512;
        int row = f >> 3, c4 = f & 7;
        float4 v = *(const float4*)&q[(size_t)row*HDM + c4*4];
        Qs[(c4*4+0)*ASTR + row] = tf32cvt(v.x);
        Qs[(c4*4+1)*ASTR + row] = tf32cvt(v.y);
        Qs[(c4*4+2)*ASTR + row] = tf32cvt(v.z);
        Qs[(c4*4+3)*ASTR + row] = tf32cvt(v.w);
    }
    if (tid < 128) mr[tid] = g_md[n*GD + tid];
    mc[tid] = g_mp[n*GP + tid];

    for (int jt = 0; jt < 4; jt++) {
        int j0 = jt * 128;
#pragma unroll
        for (int s = 0; s < 2; s++) {
            int f = tid + s*512;
            int row = f >> 3, c4 = f & 7;
            float4 v = *(const float4*)&k[(size_t)(j0+row)*HDM + c4*4];
            Ks[(c4*4+0)*ASTR + row] = tf32cvt(v.x);
            Ks[(c4*4+1)*ASTR + row] = tf32cvt(v.y);
            Ks[(c4*4+2)*ASTR + row] = tf32cvt(v.z);
            Ks[(c4*4+3)*ASTR + row] = tf32cvt(v.w);
        }
        __syncthreads();

        float c[2][4][4];
#pragma unroll
        for (int mi = 0; mi < 2; mi++)
#pragma unroll
            for (int ni = 0; ni < 4; ni++)
#pragma unroll
                for (int r = 0; r < 4; r++) c[mi][ni][r] = 0.0f;

#pragma unroll
        for (int kh = 0; kh < 4; kh++) {
            int kb = kh*8;
            uint32_t aH[2][4];
#pragma unroll
            for (int mi = 0; mi < 2; mi++) {
                int rb = wm + mi*16 + g;
                aH[mi][0] = Qs[(kb+tk  )*ASTR + rb];
                aH[mi][1] = Qs[(kb+tk  )*ASTR + rb + 8];
                aH[mi][2] = Qs[(kb+tk+4)*ASTR + rb];
                aH[mi][3] = Qs[(kb+tk+4)*ASTR + rb + 8];
            }
            uint32_t bH[4][2];
#pragma unroll
            for (int ni = 0; ni < 4; ni++) {
                int nb = wn + ni*8 + g;
                bH[ni][0] = Ks[(kb+tk  )*ASTR + nb];
                bH[ni][1] = Ks[(kb+tk+4)*ASTR + nb];
            }
#pragma unroll
            for (int mi = 0; mi < 2; mi++)
#pragma unroll
                for (int ni = 0; ni < 4; ni++) {
                    float* cc = c[mi][ni];
                    mma_tf32(cc[0],cc[1],cc[2],cc[3],
                             aH[mi][0],aH[mi][1],aH[mi][2],aH[mi][3],
                             bH[ni][0],bH[ni][1]);
                }
        }

#pragma unroll
        for (int mi = 0; mi < 2; mi++) {
            int row1 = wm + mi*16 + g;
            int row2 = row1 + 8;
            float rm1 = mr[row1], rm2 = mr[row2];
#pragma unroll
            for (int ni = 0; ni < 4; ni++) {
                int o  = wn + ni*8 + 2*tk;
                int oc = j0 + o;
                float m0v = mc[oc], m1v = mc[oc+1];
                float* cc = c[mi][ni];
                __half2 xa = __floats2half2_rn(cc[0]*EXPSC, cc[1]*EXPSC);
                uint32_t ea = ex2_f16x2(*(uint32_t*)&xa);
                __half2 ma = __floats2half2_rn(rm1*m0v, rm1*m1v);
                *(__half2*)&Esm[row1*ESTR + oc] = __hmul2(*(__half2*)&ea, ma);
                __half2 xb = __floats2half2_rn(cc[2]*EXPSC, cc[3]*EXPSC);
                uint32_t eb = ex2_f16x2(*(uint32_t*)&xb);
                __half2 mb = __floats2half2_rn(rm2*m0v, rm2*m1v);
                *(__half2*)&Esm[row2*ESTR + oc] = __hmul2(*(__half2*)&eb, mb);
            }
        }
        __syncthreads();
    }

    // ---- 4 Sinkhorn iterations out of smem ----
    float cv[16];
#pragma unroll
    for (int u = 0; u < 16; u++) cv[u] = 1.0f;

    for (int iter = 0; iter < 4; iter++) {
        float colacc[16];
#pragma unroll
        for (int u = 0; u < 16; u++) colacc[u] = 0.0f;

#pragma unroll
        for (int ridx = 0; ridx < 8; ridx++) {
            int i = w + ridx*16;
            const uint4* rp = (const uint4*)(Esm + (size_t)i * ESTR);
            float ev[16];
            float s = 0.0f;
            uint4 raws[2];
#pragma unroll
            for (int ch = 0; ch < 2; ch++) {
                uint4 raw = rp[ch*32 + lane];
                raws[ch] = raw;
                float2 f0 = __half22float2(*(__half2*)&raw.x);
                float2 f1 = __half22float2(*(__half2*)&raw.y);
                float2 f2 = __half22float2(*(__half2*)&raw.z);
                float2 f3 = __half22float2(*(__half2*)&raw.w);
                ev[ch*8+0] = f0.x; ev[ch*8+1] = f0.y;
                ev[ch*8+2] = f1.x; ev[ch*8+3] = f1.y;
                ev[ch*8+4] = f2.x; ev[ch*8+5] = f2.y;
                ev[ch*8+6] = f3.x; ev[ch*8+7] = f3.y;
            }
#pragma unroll
            for (int u = 0; u < 16; u++) s += ev[u] * cv[u];
#pragma unroll
            for (int off = 16; off > 0; off >>= 1)
                s += __shfl_xor_sync(0xFFFFFFFFu, s, off);
            float r = (s > 0.0f) ? 1.0f/s : 0.0f;
            if (iter == 3) {
                if (lane == 0) g_r[slice*GD + i] = r;
                uint4* gp = (uint4*)(g_E + (size_t)slice*GD*GP + (size_t)i*GP);
                gp[lane]      = raws[0];
                gp[32 + lane] = raws[1];
            }
#pragma unroll
            for (int u = 0; u < 16; u++) colacc[u] += r * ev[u];
        }
#pragma unroll
        for (int u = 0; u < 16; u++) {
            int cc = (u >> 3)*256 + lane*8 + (u & 7);
            strip[w*544 + SIDX(cc)] = colacc[u];
        }
        __syncthreads();
        {
            int cc = tid;
            float s2 = 0.0f;
#pragma unroll
            for (int ww = 0; ww < 16; ww++) s2 += strip[ww*544 + SIDX(cc)];
            float rec = (s2 > 0.0f) ? 1.0f/s2 : 0.0f;
            if (iter == 3) g_c[slice*GP + cc] = rec;
            else           strip[SIDX(cc)] = rec;
        }
        __syncthreads();
        if (iter < 3) {
#pragma unroll
            for (int u = 0; u < 16; u++) {
                int cc = (u >> 3)*256 + lane*8 + (u & 7);
                cv[u] = strip[SIDX(cc)];
            }
            __syncthreads();
        }
    }
}

// ---------------- write a_dp = diag(r) E diag(c) in [n,i,j,h] layout --------------
__global__ __launch_bounds__(256) void k_adp(float* __restrict__ out) {
    __shared__ __half shE[8][512];
    __shared__ float  csh[8][512];
    __shared__ float  rsh[8];
    int b = blockIdx.x;
    int n = b >> 7, i = b & 127;
    int tid = threadIdx.x;

    if (tid < 8) rsh[tid] = g_r[(n*8 + tid)*GD + i];
#pragma unroll
    for (int t = 0; t < 2; t++) {
        int f = t*256 + tid;
        int h = f >> 6, qq = f & 63;
        ((uint4*)&shE[h][0])[qq] =
            ((const uint4*)(g_E + ((size_t)(n*8 + h)*GD + i)*GP))[qq];
    }
#pragma unroll
    for (int t = 0; t < 4; t++) {
        int f = t*256 + tid;
        int h = f >> 7, j4 = f & 127;
        ((float4*)&csh[h][0])[j4] =
            ((const float4*)(g_c + (size_t)(n*8 + h)*GP))[j4];
    }
    __syncthreads();

    float* dst = out + (size_t)b * GP * 8;
#pragma unroll
    for (int t = 0; t < 16; t++) {
        int o = t*256 + tid;
        int j = o >> 3, h = o & 7;
        float e = __half2float(shE[h][j]);
        dst[o] = rsh[h] * e * csh[h][j];
    }
}

// ---------------- launch -----------------------------------------------------------
extern "C" void kernel_launch(void* const* d_in, const int* in_sizes, int n_in,
                              void* d_out, int out_size) {
    const float* protein = (const float*)d_in[0];
    const float* drug    = (const float*)d_in[1];
    const void*  maskp   = d_in[2];
    const void*  maskd   = d_in[3];
    const float* Wk_p    = (const float*)d_in[5];
    const float* Wv_p    = (const float*)d_in[6];
    const float* Wq_d    = (const float*)d_in[7];
    const float* Wv_d    = (const float*)d_in[9];
    float* out = (float*)d_out;

    size_t adp_elems = (size_t)NB * GD * GP * HN;
    int  write_q   = (((size_t)out_size > adp_elems) || ((size_t)out_size < adp_elems)) ? 1 : 0;
    bool write_adp = ((size_t)out_size >= adp_elems);
    size_t adp_off = ((size_t)out_size >= adp_elems + NB*512) ? (size_t)NB*512 : 0;

    static int smem_set = 0;
    if (!smem_set) {
        cudaFuncSetAttribute(k_mega, cudaFuncAttributeMaxDynamicSharedMemorySize, SM_TOT);
        smem_set = 1;
    }

    k_probe<<<1, 256>>>((const unsigned int*)maskp);
    k_fuse1<<<768, 256>>>(protein, drug, maskp, maskd, Wk_p, Wq_d);
    k_mega<<<NHS + NB, 512, SM_TOT>>>(Wv_p, Wv_d, out, write_q);
    if (write_adp) {
        k_adp<<<NB*GD, 256>>>(out + adp_off);
    }
}

// round 13
// speedup vs baseline: 1.2898x; 1.2898x over previous
#include <cuda_runtime.h>
#include <cuda_fp16.h>
#include <cstdint>

// ---------------- problem constants ----------------
#define NB  16
#define HN  8
#define HDM 32
#define DM  256
#define GP  512
#define GD  128
#define NHS 128          // NB*HN slices
#define SEG 16
// (1/sqrt(32)) * log2(e)
#define EXPSC 0.2550526808750678f

// swizzled smem index: conflict-free for sink strip pattern
#define SIDX(c) ((((c) & 31) * 17) + ((c) >> 5))

// mega-kernel shared memory layout (bytes)
#define ESTR   520                       // halfs per E row (1040B: +4 banks/row)
#define SM_E   0                         // 128*520*2 = 133120
#define SM_QK  133120                    // Qs 32*137*4 =17536 ; Ks +17536 (strips alias)
#define SM_MR  168192                    // float[128]
#define SM_MC  168704                    // float[512]
#define SM_TOT 170752

// ---------------- scratch (static device globals; no runtime alloc) ------------
__device__ float  g_pg[NB*GP*DM];
__device__ float  g_dg[NB*GD*DM];
__device__ float  g_mp[NB*GP];
__device__ float  g_md[NB*GD];
__device__ float  g_part[2*NB*SEG*DM];
__device__ float  g_cpart[2*NB*SEG];
__device__ float  g_kp[NHS*GP*HDM];
__device__ float  g_qd[NHS*GD*HDM];
__device__ __half g_E [NHS*GD*GP];
__device__ float  g_r [NHS*GD];
__device__ float  g_c [NHS*GP];
__device__ int    g_maskmode;

// ---------------- tf32 + mma + ex2 helpers ---------------------------------------
__device__ __forceinline__ uint32_t tf32cvt(float x) {
    uint32_t r;
    asm("cvt.rna.tf32.f32 %0, %1;" : "=r"(r) : "f"(x));
    return r;
}
__device__ __forceinline__ void mma_tf32(float& c0, float& c1, float& c2, float& c3,
                                         uint32_t a0, uint32_t a1, uint32_t a2, uint32_t a3,
                                         uint32_t b0, uint32_t b1) {
    asm volatile(
        "mma.sync.aligned.m16n8k8.row.col.f32.tf32.tf32.f32 "
        "{%0,%1,%2,%3}, {%4,%5,%6,%7}, {%8,%9}, {%0,%1,%2,%3};"
        : "+f"(c0), "+f"(c1), "+f"(c2), "+f"(c3)
        : "r"(a0), "r"(a1), "r"(a2), "r"(a3), "r"(b0), "r"(b1));
}
__device__ __forceinline__ uint32_t ex2_f16x2(uint32_t x) {
    uint32_t r;
    asm("ex2.approx.f16x2 %0, %1;" : "=r"(r) : "r"(x));
    return r;
}

// ---------------- mask dtype probe ------------------------------------------------
__global__ void k_probe(const unsigned int* __restrict__ m) {
    __shared__ int cnt[4];
    int t = threadIdx.x;
    if (t < 4) cnt[t] = 0;
    __syncthreads();
    unsigned w = m[t];
    if (w == 0x3F803F80u || w == 0x3C003C00u) atomicAdd(&cnt[0], 1);
    if (w == 0x3F800000u)                     atomicAdd(&cnt[1], 1);
    if (w > 1u)                               atomicAdd(&cnt[2], 1);
    __syncthreads();
    if (t == 0) {
        int mode;
        if (cnt[0] >= 4)      mode = 3;
        else if (cnt[1] >= 4) mode = 0;
        else if (cnt[2] > 0)  mode = 2;
        else                  mode = 1;
        g_maskmode = mode;
    }
}

__device__ __forceinline__ float mask_at(const void* M, int tok, int mode) {
    switch (mode) {
        case 0:  return ((const float*)M)[tok] != 0.0f ? 1.0f : 0.0f;
        case 1:  return ((const int*)M)[tok]   != 0    ? 1.0f : 0.0f;
        case 2:  return ((const unsigned char*)M)[tok] ? 1.0f : 0.0f;
        default: return ((const unsigned short*)M)[tok] ? 1.0f : 0.0f;
    }
}

// ---------------- grouping --------------------------------------------------------
__global__ void k_group2(const float* __restrict__ P, const float* __restrict__ Dr,
                         const void* __restrict__ MP, const void* __restrict__ MD) {
    int b = blockIdx.x;
    const float* X; const void* M; float* out; float* mout;
    if (b < NB*GP) { X = P;  M = MP; out = g_pg; mout = g_mp; }
    else           { b -= NB*GP; X = Dr; M = MD; out = g_dg; mout = g_md; }
    int d = threadIdx.x;
    const float* src = X + (size_t)b * 4 * DM;
    out[(size_t)b * DM + d] =
        0.25f * (src[d] + src[DM + d] + src[2*DM + d] + src[3*DM + d]);
    if (d == 0) {
        int mode = g_maskmode;
        float m = mask_at(M, 4*b+0, mode) + mask_at(M, 4*b+1, mode)
                + mask_at(M, 4*b+2, mode) + mask_at(M, 4*b+3, mode);
        mout[b] = (m > 0.0f) ? 1.0f : 0.0f;
    }
}

// ---------------- fused launch 1: masked-sum partials + projection GEMM ----------
#define ASTR 137
__global__ __launch_bounds__(256) void k_fuse1(const float* __restrict__ Wkp,
                                               const float* __restrict__ Wqd) {
    if (blockIdx.x < 512) {
        int s = blockIdx.x;
        int n = s & 15, ent = (s >> 4) & 1, seg = s >> 5;
        int d = threadIdx.x;
        const float* X = ent ? g_dg : g_pg;
        const float* m = ent ? g_md : g_mp;
        int G = ent ? GD : GP;
        int chunk = G / SEG;
        int g0 = seg * chunk;
        float a0 = 0.f, a1 = 0.f, a2 = 0.f, a3 = 0.f;
        for (int g = g0; g < g0 + chunk; g += 4) {
            a0 += m[n*G+g+0] * X[((size_t)(n*G+g+0))*DM + d];
            a1 += m[n*G+g+1] * X[((size_t)(n*G+g+1))*DM + d];
            a2 += m[n*G+g+2] * X[((size_t)(n*G+g+2))*DM + d];
            a3 += m[n*G+g+3] * X[((size_t)(n*G+g+3))*DM + d];
        }
        g_part[((ent*NB + n)*SEG + seg)*DM + d] = (a0 + a1) + (a2 + a3);
        if (d == 0) {
            float c = 0.0f;
            for (int g = g0; g < g0 + chunk; g++) c += m[n*G + g];
            g_cpart[(ent*NB + n)*SEG + seg] = c;
        }
        return;
    }
    int pb = blockIdx.x - 512;
    int bx = pb & 63, by = (pb >> 6) & 1, bz = pb >> 7;
    const float* X; const float* W; float* OUT; int L;
    if (bz == 0) { X = g_pg; W = Wkp; OUT = g_kp; L = GP; }
    else         { if (bx >= 16) return;
                   X = g_dg; W = Wqd; OUT = g_qd; L = GD; }
    __shared__ uint32_t AsH[32*ASTR];
    __shared__ uint32_t BsH[32*ASTR];

    int tid = threadIdx.x;
    int lane = tid & 31, w = tid >> 5;
    int g = lane >> 2, tk = lane & 3;
    int wm = (w & 3) * 32, wn = (w >> 2) * 64;
    int m0 = bx * 128, o0 = by * 128;

    float c[2][8][4];
#pragma unroll
    for (int mi = 0; mi < 2; mi++)
#pragma unroll
        for (int ni = 0; ni < 8; ni++)
#pragma unroll
            for (int r = 0; r < 4; r++) c[mi][ni][r] = 0.0f;

    for (int k0 = 0; k0 < 256; k0 += 32) {
#pragma unroll
        for (int s = 0; s < 4; s++) {
            int f = tid + s*256;
            int row = f >> 3, c4 = f & 7;
            float4 va = *(const float4*)&X[(size_t)(m0+row)*256 + k0 + c4*4];
            AsH[(c4*4+0)*ASTR + row] = tf32cvt(va.x);
            AsH[(c4*4+1)*ASTR + row] = tf32cvt(va.y);
            AsH[(c4*4+2)*ASTR + row] = tf32cvt(va.z);
            AsH[(c4*4+3)*ASTR + row] = tf32cvt(va.w);
            float4 vb = *(const float4*)&W[(size_t)(o0+row)*256 + k0 + c4*4];
            BsH[(c4*4+0)*ASTR + row] = tf32cvt(vb.x);
            BsH[(c4*4+1)*ASTR + row] = tf32cvt(vb.y);
            BsH[(c4*4+2)*ASTR + row] = tf32cvt(vb.z);
            BsH[(c4*4+3)*ASTR + row] = tf32cvt(vb.w);
        }
        __syncthreads();
#pragma unroll
        for (int kh = 0; kh < 4; kh++) {
            int kb = kh*8;
            uint32_t aH[2][4];
#pragma unroll
            for (int mi = 0; mi < 2; mi++) {
                int rb = wm + mi*16 + g;
                aH[mi][0] = AsH[(kb+tk  )*ASTR + rb];
                aH[mi][1] = AsH[(kb+tk  )*ASTR + rb + 8];
                aH[mi][2] = AsH[(kb+tk+4)*ASTR + rb];
                aH[mi][3] = AsH[(kb+tk+4)*ASTR + rb + 8];
            }
            uint32_t bH[8][2];
#pragma unroll
            for (int ni = 0; ni < 8; ni++) {
                int nb = wn + ni*8 + g;
                bH[ni][0] = BsH[(kb+tk  )*ASTR + nb];
                bH[ni][1] = BsH[(kb+tk+4)*ASTR + nb];
            }
#pragma unroll
            for (int mi = 0; mi < 2; mi++)
#pragma unroll
                for (int ni = 0; ni < 8; ni++) {
                    float* cc = c[mi][ni];
                    mma_tf32(cc[0],cc[1],cc[2],cc[3],
                             aH[mi][0],aH[mi][1],aH[mi][2],aH[mi][3],
                             bH[ni][0],bH[ni][1]);
                }
        }
        __syncthreads();
    }

#pragma unroll
    for (int mi = 0; mi < 2; mi++)
#pragma unroll
        for (int ni = 0; ni < 8; ni++) {
            int o = o0 + wn + ni*8 + 2*tk;
            int h = o >> 5, dd = o & 31;
            int m = m0 + wm + mi*16 + g;
            int nb = m / L, gg = m % L;
            float* dst = &OUT[(((size_t)(nb*HN + h))*L + gg)*HDM + dd];
            *(float2*)dst = make_float2(c[mi][ni][0], c[mi][ni][1]);
            int m2 = m + 8;
            int nb2 = m2 / L, gg2 = m2 % L;
            float* dst2 = &OUT[(((size_t)(nb2*HN + h))*L + gg2)*HDM + dd];
            *(float2*)dst2 = make_float2(c[mi][ni][2], c[mi][ni][3]);
        }
}

// ---------------- mega kernel: logits (TF32 MMA) + 4x Sinkhorn, E in smem ---------
__global__ __launch_bounds__(512) void k_mega(const float* __restrict__ Wvp,
                                              const float* __restrict__ Wvd,
                                              float* __restrict__ qout, int do_q) {
    extern __shared__ char smem[];
    int tid = threadIdx.x;
    int lane = tid & 31, w = tid >> 5;

    if (blockIdx.x >= NHS) {
        if (!do_q) return;
        float* sp   = (float*)smem;
        float* sd   = sp + DM;
        float* cnts = sd + DM;
        int n = blockIdx.x - NHS;
        if (tid < DM) {
            float accp = 0.0f, accd = 0.0f;
#pragma unroll
            for (int s = 0; s < SEG; s++) {
                accp += g_part[((0*NB + n)*SEG + s)*DM + tid];
                accd += g_part[((1*NB + n)*SEG + s)*DM + tid];
            }
            sp[tid] = accp; sd[tid] = accd;
        }
        if (tid < 2) {
            float c = 0.0f;
#pragma unroll
            for (int s = 0; s < SEG; s++) c += g_cpart[(tid*NB + n)*SEG + s];
            cnts[tid] = c;
        }
        __syncthreads();
        float cp = cnts[0], cd = cnts[1];
        for (int o = w; o < DM; o += 16) {
            float acc = 0.0f;
#pragma unroll
            for (int t = 0; t < 8; t++) {
                int k = lane + t*32;
                acc += sp[k]*Wvp[(size_t)o*DM + k] + sd[k]*Wvd[(size_t)o*DM + k];
            }
#pragma unroll
            for (int off = 16; off > 0; off >>= 1)
                acc += __shfl_xor_sync(0xFFFFFFFFu, acc, off);
            if (lane == 0) {
                qout[(size_t)n*512 + o]       = 0.5f * acc / cp;
                qout[(size_t)n*512 + 256 + o] = 0.5f * acc / cd;
            }
        }
        return;
    }

    // ---- per-slice logits + Sinkhorn ----
    int slice = blockIdx.x;
    int n = slice >> 3;
    const float* q = g_qd + (size_t)slice * GD * HDM;
    const float* k = g_kp + (size_t)slice * GP * HDM;

    __half*   Esm   = (__half*)(smem + SM_E);
    uint32_t* Qs    = (uint32_t*)(smem + SM_QK);
    uint32_t* Ks    = Qs + 32*ASTR;
    float*    strip = (float*)(smem + SM_QK);
    float*    mr    = (float*)(smem + SM_MR);
    float*    mc    = (float*)(smem + SM_MC);

    int g = lane >> 2, tk = lane & 3;
    int wm = (w & 3) * 32, wn = (w >> 2) * 32;

#pragma unroll
    for (int s = 0; s < 2; s++) {
        int f = tid + s*512;
        int row = f >> 3, c4 = f & 7;
        float4 v = *(const float4*)&q[(size_t)row*HDM + c4*4];
        Qs[(c4*4+0)*ASTR + row] = tf32cvt(v.x);
        Qs[(c4*4+1)*ASTR + row] = tf32cvt(v.y);
        Qs[(c4*4+2)*ASTR + row] = tf32cvt(v.z);
        Qs[(c4*4+3)*ASTR + row] = tf32cvt(v.w);
    }
    if (tid < 128) mr[tid] = g_md[n*GD + tid];
    mc[tid] = g_mp[n*GP + tid];

    for (int jt = 0; jt < 4; jt++) {
        int j0 = jt * 128;
#pragma unroll
        for (int s = 0; s < 2; s++) {
            int f = tid + s*512;
            int row = f >> 3, c4 = f & 7;
            float4 v = *(const float4*)&k[(size_t)(j0+row)*HDM + c4*4];
            Ks[(c4*4+0)*ASTR + row] = tf32cvt(v.x);
            Ks[(c4*4+1)*ASTR + row] = tf32cvt(v.y);
            Ks[(c4*4+2)*ASTR + row] = tf32cvt(v.z);
            Ks[(c4*4+3)*ASTR + row] = tf32cvt(v.w);
        }
        __syncthreads();

        float c[2][4][4];
#pragma unroll
        for (int mi = 0; mi < 2; mi++)
#pragma unroll
            for (int ni = 0; ni < 4; ni++)
#pragma unroll
                for (int r = 0; r < 4; r++) c[mi][ni][r] = 0.0f;

#pragma unroll
        for (int kh = 0; kh < 4; kh++) {
            int kb = kh*8;
            uint32_t aH[2][4];
#pragma unroll
            for (int mi = 0; mi < 2; mi++) {
                int rb = wm + mi*16 + g;
                aH[mi][0] = Qs[(kb+tk  )*ASTR + rb];
                aH[mi][1] = Qs[(kb+tk  )*ASTR + rb + 8];
                aH[mi][2] = Qs[(kb+tk+4)*ASTR + rb];
                aH[mi][3] = Qs[(kb+tk+4)*ASTR + rb + 8];
            }
            uint32_t bH[4][2];
#pragma unroll
            for (int ni = 0; ni < 4; ni++) {
                int nb = wn + ni*8 + g;
                bH[ni][0] = Ks[(kb+tk  )*ASTR + nb];
                bH[ni][1] = Ks[(kb+tk+4)*ASTR + nb];
            }
#pragma unroll
            for (int mi = 0; mi < 2; mi++)
#pragma unroll
                for (int ni = 0; ni < 4; ni++) {
                    float* cc = c[mi][ni];
                    mma_tf32(cc[0],cc[1],cc[2],cc[3],
                             aH[mi][0],aH[mi][1],aH[mi][2],aH[mi][3],
                             bH[ni][0],bH[ni][1]);
                }
        }

#pragma unroll
        for (int mi = 0; mi < 2; mi++) {
            int row1 = wm + mi*16 + g;
            int row2 = row1 + 8;
            float rm1 = mr[row1], rm2 = mr[row2];
#pragma unroll
            for (int ni = 0; ni < 4; ni++) {
                int o  = wn + ni*8 + 2*tk;
                int oc = j0 + o;
                float m0v = mc[oc], m1v = mc[oc+1];
                float* cc = c[mi][ni];
                __half2 xa = __floats2half2_rn(cc[0]*EXPSC, cc[1]*EXPSC);
                uint32_t ea = ex2_f16x2(*(uint32_t*)&xa);
                __half2 ma = __floats2half2_rn(rm1*m0v, rm1*m1v);
                *(__half2*)&Esm[row1*ESTR + oc] = __hmul2(*(__half2*)&ea, ma);
                __half2 xb = __floats2half2_rn(cc[2]*EXPSC, cc[3]*EXPSC);
                uint32_t eb = ex2_f16x2(*(uint32_t*)&xb);
                __half2 mb = __floats2half2_rn(rm2*m0v, rm2*m1v);
                *(__half2*)&Esm[row2*ESTR + oc] = __hmul2(*(__half2*)&eb, mb);
            }
        }
        __syncthreads();
    }

    // ---- 4 Sinkhorn iterations out of smem ----
    float cv[16];
#pragma unroll
    for (int u = 0; u < 16; u++) cv[u] = 1.0f;

    for (int iter = 0; iter < 4; iter++) {
        float colacc[16];
#pragma unroll
        for (int u = 0; u < 16; u++) colacc[u] = 0.0f;

#pragma unroll
        for (int ridx = 0; ridx < 8; ridx++) {
            int i = w + ridx*16;
            const uint4* rp = (const uint4*)(Esm + (size_t)i * ESTR);
            float ev[16];
            float s = 0.0f;
            uint4 raws[2];
#pragma unroll
            for (int ch = 0; ch < 2; ch++) {
                uint4 raw = rp[ch*32 + lane];
                raws[ch] = raw;
                float2 f0 = __half22float2(*(__half2*)&raw.x);
                float2 f1 = __half22float2(*(__half2*)&raw.y);
                float2 f2 = __half22float2(*(__half2*)&raw.z);
                float2 f3 = __half22float2(*(__half2*)&raw.w);
                ev[ch*8+0] = f0.x; ev[ch*8+1] = f0.y;
                ev[ch*8+2] = f1.x; ev[ch*8+3] = f1.y;
                ev[ch*8+4] = f2.x; ev[ch*8+5] = f2.y;
                ev[ch*8+6] = f3.x; ev[ch*8+7] = f3.y;
            }
#pragma unroll
            for (int u = 0; u < 16; u++) s += ev[u] * cv[u];
#pragma unroll
            for (int off = 16; off > 0; off >>= 1)
                s += __shfl_xor_sync(0xFFFFFFFFu, s, off);
            float r = (s > 0.0f) ? 1.0f/s : 0.0f;
            if (iter == 3) {
                if (lane == 0) g_r[slice*GD + i] = r;
                uint4* gp = (uint4*)(g_E + (size_t)slice*GD*GP + (size_t)i*GP);
                gp[lane]      = raws[0];
                gp[32 + lane] = raws[1];
            }
#pragma unroll
            for (int u = 0; u < 16; u++) colacc[u] += r * ev[u];
        }
#pragma unroll
        for (int u = 0; u < 16; u++) {
            int cc = (u >> 3)*256 + lane*8 + (u & 7);
            strip[w*544 + SIDX(cc)] = colacc[u];
        }
        __syncthreads();
        {
            int cc = tid;
            float s2 = 0.0f;
#pragma unroll
            for (int ww = 0; ww < 16; ww++) s2 += strip[ww*544 + SIDX(cc)];
            float rec = (s2 > 0.0f) ? 1.0f/s2 : 0.0f;
            if (iter == 3) g_c[slice*GP + cc] = rec;
            else           strip[SIDX(cc)] = rec;
        }
        __syncthreads();
        if (iter < 3) {
#pragma unroll
            for (int u = 0; u < 16; u++) {
                int cc = (u >> 3)*256 + lane*8 + (u & 7);
                cv[u] = strip[SIDX(cc)];
            }
            __syncthreads();
        }
    }
}

// ---------------- write a_dp = diag(r) E diag(c), conflict-free staging ----------
// stride 516 floats: bank(h*516 + j) = (4h + j) mod 32 -> bijective over a warp.
#define CSTR 516
__global__ __launch_bounds__(256) void k_adp(float* __restrict__ out) {
    __shared__ float shEf[8*CSTR];      // E rows as float
    __shared__ float cshr[8*CSTR];      // c reciprocals
    __shared__ float rsh[8];
    int b = blockIdx.x;
    int n = b >> 7, i = b & 127;
    int tid = threadIdx.x;

    if (tid < 8) rsh[tid] = g_r[(n*8 + tid)*GD + i];
#pragma unroll
    for (int t = 0; t < 2; t++) {
        int f = t*256 + tid;               // 0..511
        int h = f >> 6, qq = f & 63;       // 64 uint4 (8 halfs) per 512-half row
        uint4 raw = ((const uint4*)(g_E + ((size_t)(n*8 + h)*GD + i)*GP))[qq];
        float2 f0 = __half22float2(*(__half2*)&raw.x);
        float2 f1 = __half22float2(*(__half2*)&raw.y);
        float2 f2 = __half22float2(*(__half2*)&raw.z);
        float2 f3 = __half22float2(*(__half2*)&raw.w);
        float* dstE = &shEf[h*CSTR + qq*8];
        ((float4*)dstE)[0] = make_float4(f0.x, f0.y, f1.x, f1.y);
        ((float4*)dstE)[1] = make_float4(f2.x, f2.y, f3.x, f3.y);
    }
#pragma unroll
    for (int t = 0; t < 4; t++) {
        int f = t*256 + tid;               // 0..1023
        int h = f >> 7, j4 = f & 127;      // 128 float4 per 512-float row
        ((float4*)&cshr[h*CSTR])[j4] =
            ((const float4*)(g_c + (size_t)(n*8 + h)*GP))[j4];
    }
    __syncthreads();

    float* dst = out + (size_t)b * GP * 8;
#pragma unroll
    for (int t = 0; t < 16; t++) {
        int o = t*256 + tid;
        int j = o >> 3, h = o & 7;
        dst[o] = rsh[h] * shEf[h*CSTR + j] * cshr[h*CSTR + j];
    }
}

// ---------------- launch -----------------------------------------------------------
extern "C" void kernel_launch(void* const* d_in, const int* in_sizes, int n_in,
                              void* d_out, int out_size) {
    const float* protein = (const float*)d_in[0];
    const float* drug    = (const float*)d_in[1];
    const void*  maskp   = d_in[2];
    const void*  maskd   = d_in[3];
    const float* Wk_p    = (const float*)d_in[5];
    const float* Wv_p    = (const float*)d_in[6];
    const float* Wq_d    = (const float*)d_in[7];
    const float* Wv_d    = (const float*)d_in[9];
    float* out = (float*)d_out;

    size_t adp_elems = (size_t)NB * GD * GP * HN;
    int  write_q   = (((size_t)out_size > adp_elems) || ((size_t)out_size < adp_elems)) ? 1 : 0;
    bool write_adp = ((size_t)out_size >= adp_elems);
    size_t adp_off = ((size_t)out_size >= adp_elems + NB*512) ? (size_t)NB*512 : 0;

    static int smem_set = 0;
    if (!smem_set) {
        cudaFuncSetAttribute(k_mega, cudaFuncAttributeMaxDynamicSharedMemorySize, SM_TOT);
        smem_set = 1;
    }

    k_probe<<<1, 256>>>((const unsigned int*)maskp);
    k_group2<<<NB*GP + NB*GD, 256>>>(protein, drug, maskp, maskd);
    k_fuse1<<<768, 256>>>(Wk_p, Wq_d);
    k_mega<<<NHS + NB, 512, SM_TOT>>>(Wv_p, Wv_d, out, write_q);
    if (write_adp) {
        k_adp<<<NB*GD, 256>>>(out + adp_off);
    }
}

// round 14
// speedup vs baseline: 1.3080x; 1.0141x over previous
#include <cuda_runtime.h>
#include <cuda_fp16.h>
#include <cstdint>

// ---------------- problem constants ----------------
#define NB  16
#define HN  8
#define HDM 32
#define DM  256
#define GP  512
#define GD  128
#define NHS 128          // NB*HN slices
#define SEG 16
// (1/sqrt(32)) * log2(e)
#define EXPSC 0.2550526808750678f

// swizzled smem index: conflict-free for sink strip pattern
#define SIDX(c) ((((c) & 31) * 17) + ((c) >> 5))

// mega-kernel shared memory layout (bytes)
#define ESTR   520                       // halfs per E row (1040B: +4 banks/row)
#define SM_E   0                         // 128*520*2 = 133120
#define SM_QK  133120                    // Qs 32*137*4 =17536 ; Ks +17536 (strips alias)
#define SM_MR  168192                    // float[128] row biases
#define SM_MC  168704                    // float[512] col biases
#define SM_TOT 170752

// ---------------- scratch (static device globals; no runtime alloc) ------------
__device__ float  g_pg[NB*GP*DM];
__device__ float  g_dg[NB*GD*DM];
__device__ float  g_mp[NB*GP];
__device__ float  g_md[NB*GD];
__device__ float  g_part[2*NB*SEG*DM];
__device__ float  g_cpart[2*NB*SEG];
__device__ float  g_kp[NHS*GP*HDM];
__device__ float  g_qd[NHS*GD*HDM];
__device__ __half g_E [NHS*GD*GP];
__device__ float  g_r [NHS*GD];
__device__ float  g_c [NHS*GP];

// ---------------- packed f32x2 + tf32 + mma + ex2 helpers -------------------------
__device__ __forceinline__ unsigned long long pack2(float x) {
    unsigned long long r;
    asm("mov.b64 %0, {%1, %1};" : "=l"(r) : "r"(__float_as_uint(x)));
    return r;
}
__device__ __forceinline__ unsigned long long packf2(float lo, float hi) {
    unsigned long long r;
    asm("mov.b64 %0, {%1, %2};" : "=l"(r) : "f"(lo), "f"(hi));
    return r;
}
__device__ __forceinline__ void fma2(unsigned long long& d,
                                     unsigned long long a, unsigned long long b) {
    asm("fma.rn.f32x2 %0, %1, %2, %0;" : "+l"(d) : "l"(a), "l"(b));
}
__device__ __forceinline__ float2 unpack2(unsigned long long v) {
    unsigned lo, hi;
    asm("mov.b64 {%0, %1}, %2;" : "=r"(lo), "=r"(hi) : "l"(v));
    return make_float2(__uint_as_float(lo), __uint_as_float(hi));
}
__device__ __forceinline__ uint32_t tf32cvt(float x) {
    uint32_t r;
    asm("cvt.rna.tf32.f32 %0, %1;" : "=r"(r) : "f"(x));
    return r;
}
__device__ __forceinline__ void mma_tf32(float& c0, float& c1, float& c2, float& c3,
                                         uint32_t a0, uint32_t a1, uint32_t a2, uint32_t a3,
                                         uint32_t b0, uint32_t b1) {
    asm volatile(
        "mma.sync.aligned.m16n8k8.row.col.f32.tf32.tf32.f32 "
        "{%0,%1,%2,%3}, {%4,%5,%6,%7}, {%8,%9}, {%0,%1,%2,%3};"
        : "+f"(c0), "+f"(c1), "+f"(c2), "+f"(c3)
        : "r"(a0), "r"(a1), "r"(a2), "r"(a3), "r"(b0), "r"(b1));
}
__device__ __forceinline__ uint32_t ex2_f16x2(uint32_t x) {
    uint32_t r;
    asm("ex2.approx.f16x2 %0, %1;" : "=r"(r) : "r"(x));
    return r;
}

__device__ __forceinline__ float mask_at(const void* M, int tok, int mode) {
    switch (mode) {
        case 0:  return ((const float*)M)[tok] != 0.0f ? 1.0f : 0.0f;
        case 1:  return ((const int*)M)[tok]   != 0    ? 1.0f : 0.0f;
        case 2:  return ((const unsigned char*)M)[tok] ? 1.0f : 0.0f;
        default: return ((const unsigned short*)M)[tok] ? 1.0f : 0.0f;
    }
}

// ---------------- grouping (with inline per-block mask-dtype probe) ----------------
__global__ void k_group2(const float* __restrict__ P, const float* __restrict__ Dr,
                         const void* __restrict__ MP, const void* __restrict__ MD) {
    __shared__ int cnt[4];
    int d = threadIdx.x;
    if (d < 4) cnt[d] = 0;
    __syncthreads();
    {
        unsigned wmk = ((const unsigned int*)MP)[d];
        if (wmk == 0x3F803F80u || wmk == 0x3C003C00u) atomicAdd(&cnt[0], 1);
        if (wmk == 0x3F800000u)                       atomicAdd(&cnt[1], 1);
        if (wmk > 1u)                                 atomicAdd(&cnt[2], 1);
    }
    __syncthreads();

    int b = blockIdx.x;
    const float* X; const void* M; float* out; float* mout;
    if (b < NB*GP) { X = P;  M = MP; out = g_pg; mout = g_mp; }
    else           { b -= NB*GP; X = Dr; M = MD; out = g_dg; mout = g_md; }
    const float* src = X + (size_t)b * 4 * DM;
    out[(size_t)b * DM + d] =
        0.25f * (src[d] + src[DM + d] + src[2*DM + d] + src[3*DM + d]);
    if (d == 0) {
        int mode;
        if (cnt[0] >= 4)      mode = 3;
        else if (cnt[1] >= 4) mode = 0;
        else if (cnt[2] > 0)  mode = 2;
        else                  mode = 1;
        float m = mask_at(M, 4*b+0, mode) + mask_at(M, 4*b+1, mode)
                + mask_at(M, 4*b+2, mode) + mask_at(M, 4*b+3, mode);
        mout[b] = (m > 0.0f) ? 1.0f : 0.0f;
    }
}

// ---------------- fused launch 1: masked-sum partials + projection GEMM ----------
#define ASTR 137
__global__ __launch_bounds__(256) void k_fuse1(const float* __restrict__ Wkp,
                                               const float* __restrict__ Wqd) {
    if (blockIdx.x < 512) {
        int s = blockIdx.x;
        int n = s & 15, ent = (s >> 4) & 1, seg = s >> 5;
        int d = threadIdx.x;
        const float* X = ent ? g_dg : g_pg;
        const float* m = ent ? g_md : g_mp;
        int G = ent ? GD : GP;
        int chunk = G / SEG;
        int g0 = seg * chunk;
        float a0 = 0.f, a1 = 0.f, a2 = 0.f, a3 = 0.f;
        for (int g = g0; g < g0 + chunk; g += 4) {
            a0 += m[n*G+g+0] * X[((size_t)(n*G+g+0))*DM + d];
            a1 += m[n*G+g+1] * X[((size_t)(n*G+g+1))*DM + d];
            a2 += m[n*G+g+2] * X[((size_t)(n*G+g+2))*DM + d];
            a3 += m[n*G+g+3] * X[((size_t)(n*G+g+3))*DM + d];
        }
        g_part[((ent*NB + n)*SEG + seg)*DM + d] = (a0 + a1) + (a2 + a3);
        if (d == 0) {
            float c = 0.0f;
            for (int g = g0; g < g0 + chunk; g++) c += m[n*G + g];
            g_cpart[(ent*NB + n)*SEG + seg] = c;
        }
        return;
    }
    int pb = blockIdx.x - 512;
    int bx = pb & 63, by = (pb >> 6) & 1, bz = pb >> 7;
    const float* X; const float* W; float* OUT; int L;
    if (bz == 0) { X = g_pg; W = Wkp; OUT = g_kp; L = GP; }
    else         { if (bx >= 16) return;
                   X = g_dg; W = Wqd; OUT = g_qd; L = GD; }
    __shared__ uint32_t AsH[32*ASTR];
    __shared__ uint32_t BsH[32*ASTR];

    int tid = threadIdx.x;
    int lane = tid & 31, w = tid >> 5;
    int g = lane >> 2, tk = lane & 3;
    int wm = (w & 3) * 32, wn = (w >> 2) * 64;
    int m0 = bx * 128, o0 = by * 128;

    float c[2][8][4];
#pragma unroll
    for (int mi = 0; mi < 2; mi++)
#pragma unroll
        for (int ni = 0; ni < 8; ni++)
#pragma unroll
            for (int r = 0; r < 4; r++) c[mi][ni][r] = 0.0f;

    for (int k0 = 0; k0 < 256; k0 += 32) {
#pragma unroll
        for (int s = 0; s < 4; s++) {
            int f = tid + s*256;
            int row = f >> 3, c4 = f & 7;
            float4 va = *(const float4*)&X[(size_t)(m0+row)*256 + k0 + c4*4];
            AsH[(c4*4+0)*ASTR + row] = tf32cvt(va.x);
            AsH[(c4*4+1)*ASTR + row] = tf32cvt(va.y);
            AsH[(c4*4+2)*ASTR + row] = tf32cvt(va.z);
            AsH[(c4*4+3)*ASTR + row] = tf32cvt(va.w);
            float4 vb = *(const float4*)&W[(size_t)(o0+row)*256 + k0 + c4*4];
            BsH[(c4*4+0)*ASTR + row] = tf32cvt(vb.x);
            BsH[(c4*4+1)*ASTR + row] = tf32cvt(vb.y);
            BsH[(c4*4+2)*ASTR + row] = tf32cvt(vb.z);
            BsH[(c4*4+3)*ASTR + row] = tf32cvt(vb.w);
        }
        __syncthreads();
#pragma unroll
        for (int kh = 0; kh < 4; kh++) {
            int kb = kh*8;
            uint32_t aH[2][4];
#pragma unroll
            for (int mi = 0; mi < 2; mi++) {
                int rb = wm + mi*16 + g;
                aH[mi][0] = AsH[(kb+tk  )*ASTR + rb];
                aH[mi][1] = AsH[(kb+tk  )*ASTR + rb + 8];
                aH[mi][2] = AsH[(kb+tk+4)*ASTR + rb];
                aH[mi][3] = AsH[(kb+tk+4)*ASTR + rb + 8];
            }
            uint32_t bH[8][2];
#pragma unroll
            for (int ni = 0; ni < 8; ni++) {
                int nb = wn + ni*8 + g;
                bH[ni][0] = BsH[(kb+tk  )*ASTR + nb];
                bH[ni][1] = BsH[(kb+tk+4)*ASTR + nb];
            }
#pragma unroll
            for (int mi = 0; mi < 2; mi++)
#pragma unroll
                for (int ni = 0; ni < 8; ni++) {
                    float* cc = c[mi][ni];
                    mma_tf32(cc[0],cc[1],cc[2],cc[3],
                             aH[mi][0],aH[mi][1],aH[mi][2],aH[mi][3],
                             bH[ni][0],bH[ni][1]);
                }
        }
        __syncthreads();
    }

#pragma unroll
    for (int mi = 0; mi < 2; mi++)
#pragma unroll
        for (int ni = 0; ni < 8; ni++) {
            int o = o0 + wn + ni*8 + 2*tk;
            int h = o >> 5, dd = o & 31;
            int m = m0 + wm + mi*16 + g;
            int nb = m / L, gg = m % L;
            float* dst = &OUT[(((size_t)(nb*HN + h))*L + gg)*HDM + dd];
            *(float2*)dst = make_float2(c[mi][ni][0], c[mi][ni][1]);
            int m2 = m + 8;
            int nb2 = m2 / L, gg2 = m2 % L;
            float* dst2 = &OUT[(((size_t)(nb2*HN + h))*L + gg2)*HDM + dd];
            *(float2*)dst2 = make_float2(c[mi][ni][2], c[mi][ni][3]);
        }
}

// ---------------- mega kernel: logits (TF32 MMA) + 4x Sinkhorn, E in smem ---------
__global__ __launch_bounds__(512) void k_mega(const float* __restrict__ Wvp,
                                              const float* __restrict__ Wvd,
                                              float* __restrict__ qout, int do_q) {
    extern __shared__ char smem[];
    int tid = threadIdx.x;
    int lane = tid & 31, w = tid >> 5;

    if (blockIdx.x >= NHS) {
        if (!do_q) return;
        float* sp   = (float*)smem;
        float* sd   = sp + DM;
        float* cnts = sd + DM;
        int n = blockIdx.x - NHS;
        if (tid < DM) {
            float accp = 0.0f, accd = 0.0f;
#pragma unroll
            for (int s = 0; s < SEG; s++) {
                accp += g_part[((0*NB + n)*SEG + s)*DM + tid];
                accd += g_part[((1*NB + n)*SEG + s)*DM + tid];
            }
            sp[tid] = accp; sd[tid] = accd;
        }
        if (tid < 2) {
            float c = 0.0f;
#pragma unroll
            for (int s = 0; s < SEG; s++) c += g_cpart[(tid*NB + n)*SEG + s];
            cnts[tid] = c;
        }
        __syncthreads();
        float cp = cnts[0], cd = cnts[1];
        for (int o = w; o < DM; o += 16) {
            float acc = 0.0f;
#pragma unroll
            for (int t = 0; t < 8; t++) {
                int k = lane + t*32;
                acc += sp[k]*Wvp[(size_t)o*DM + k] + sd[k]*Wvd[(size_t)o*DM + k];
            }
#pragma unroll
            for (int off = 16; off > 0; off >>= 1)
                acc += __shfl_xor_sync(0xFFFFFFFFu, acc, off);
            if (lane == 0) {
                qout[(size_t)n*512 + o]       = 0.5f * acc / cp;
                qout[(size_t)n*512 + 256 + o] = 0.5f * acc / cd;
            }
        }
        return;
    }

    // ---- per-slice logits + Sinkhorn ----
    int slice = blockIdx.x;
    int n = slice >> 3;
    const float* q = g_qd + (size_t)slice * GD * HDM;
    const float* k = g_kp + (size_t)slice * GP * HDM;

    __half*   Esm   = (__half*)(smem + SM_E);
    uint32_t* Qs    = (uint32_t*)(smem + SM_QK);
    uint32_t* Ks    = Qs + 32*ASTR;
    float*    strip = (float*)(smem + SM_QK);
    float*    mrb   = (float*)(smem + SM_MR);    // row biases (0 or -1e4)
    float*    mcb   = (float*)(smem + SM_MC);    // col biases

    int g = lane >> 2, tk = lane & 3;
    int wm = (w & 3) * 32, wn = (w >> 2) * 32;

#pragma unroll
    for (int s = 0; s < 2; s++) {
        int f = tid + s*512;
        int row = f >> 3, c4 = f & 7;
        float4 v = *(const float4*)&q[(size_t)row*HDM + c4*4];
        Qs[(c4*4+0)*ASTR + row] = tf32cvt(v.x);
        Qs[(c4*4+1)*ASTR + row] = tf32cvt(v.y);
        Qs[(c4*4+2)*ASTR + row] = tf32cvt(v.z);
        Qs[(c4*4+3)*ASTR + row] = tf32cvt(v.w);
    }
    if (tid < 128) mrb[tid] = (g_md[n*GD + tid] > 0.0f) ? 0.0f : -10000.0f;
    mcb[tid] = (g_mp[n*GP + tid] > 0.0f) ? 0.0f : -10000.0f;

    for (int jt = 0; jt < 4; jt++) {
        int j0 = jt * 128;
#pragma unroll
        for (int s = 0; s < 2; s++) {
            int f = tid + s*512;
            int row = f >> 3, c4 = f & 7;
            float4 v = *(const float4*)&k[(size_t)(j0+row)*HDM + c4*4];
            Ks[(c4*4+0)*ASTR + row] = tf32cvt(v.x);
            Ks[(c4*4+1)*ASTR + row] = tf32cvt(v.y);
            Ks[(c4*4+2)*ASTR + row] = tf32cvt(v.z);
            Ks[(c4*4+3)*ASTR + row] = tf32cvt(v.w);
        }
        __syncthreads();

        float c[2][4][4];
#pragma unroll
        for (int mi = 0; mi < 2; mi++)
#pragma unroll
            for (int ni = 0; ni < 4; ni++)
#pragma unroll
                for (int r = 0; r < 4; r++) c[mi][ni][r] = 0.0f;

#pragma unroll
        for (int kh = 0; kh < 4; kh++) {
            int kb = kh*8;
            uint32_t aH[2][4];
#pragma unroll
            for (int mi = 0; mi < 2; mi++) {
                int rb = wm + mi*16 + g;
                aH[mi][0] = Qs[(kb+tk  )*ASTR + rb];
                aH[mi][1] = Qs[(kb+tk  )*ASTR + rb + 8];
                aH[mi][2] = Qs[(kb+tk+4)*ASTR + rb];
                aH[mi][3] = Qs[(kb+tk+4)*ASTR + rb + 8];
            }
            uint32_t bH[4][2];
#pragma unroll
            for (int ni = 0; ni < 4; ni++) {
                int nb = wn + ni*8 + g;
                bH[ni][0] = Ks[(kb+tk  )*ASTR + nb];
                bH[ni][1] = Ks[(kb+tk+4)*ASTR + nb];
            }
#pragma unroll
            for (int mi = 0; mi < 2; mi++)
#pragma unroll
                for (int ni = 0; ni < 4; ni++) {
                    float* cc = c[mi][ni];
                    mma_tf32(cc[0],cc[1],cc[2],cc[3],
                             aH[mi][0],aH[mi][1],aH[mi][2],aH[mi][3],
                             bH[ni][0],bH[ni][1]);
                }
        }

        // epilogue: additive mask-bias + ex2.f16x2 (masked entries underflow to 0)
#pragma unroll
        for (int mi = 0; mi < 2; mi++) {
            int row1 = wm + mi*16 + g;
            int row2 = row1 + 8;
            float br1 = mrb[row1], br2 = mrb[row2];
#pragma unroll
            for (int ni = 0; ni < 4; ni++) {
                int o  = wn + ni*8 + 2*tk;
                int oc = j0 + o;
                float bc0 = mcb[oc], bc1 = mcb[oc+1];
                float* cc = c[mi][ni];
                __half2 xa = __floats2half2_rn(fmaf(cc[0], EXPSC, br1 + bc0),
                                               fmaf(cc[1], EXPSC, br1 + bc1));
                *(uint32_t*)&Esm[row1*ESTR + oc] = ex2_f16x2(*(uint32_t*)&xa);
                __half2 xb = __floats2half2_rn(fmaf(cc[2], EXPSC, br2 + bc0),
                                               fmaf(cc[3], EXPSC, br2 + bc1));
                *(uint32_t*)&Esm[row2*ESTR + oc] = ex2_f16x2(*(uint32_t*)&xb);
            }
        }
        __syncthreads();
    }

    // ---- 4 Sinkhorn iterations out of smem (packed f32x2 math) ----
    unsigned long long cv2[8];
#pragma unroll
    for (int v = 0; v < 8; v++) cv2[v] = pack2(1.0f);

    for (int iter = 0; iter < 4; iter++) {
        unsigned long long colacc2[8];
#pragma unroll
        for (int v = 0; v < 8; v++) colacc2[v] = 0ULL;

#pragma unroll
        for (int ridx = 0; ridx < 8; ridx++) {
            int i = w + ridx*16;
            const uint4* rp = (const uint4*)(Esm + (size_t)i * ESTR);
            uint4 raws[2];
            unsigned long long ev2[8];
#pragma unroll
            for (int ch = 0; ch < 2; ch++) {
                uint4 raw = rp[ch*32 + lane];
                raws[ch] = raw;
                float2 f0 = __half22float2(*(__half2*)&raw.x);
                float2 f1 = __half22float2(*(__half2*)&raw.y);
                float2 f2 = __half22float2(*(__half2*)&raw.z);
                float2 f3 = __half22float2(*(__half2*)&raw.w);
                ev2[ch*4+0] = packf2(f0.x, f0.y);
                ev2[ch*4+1] = packf2(f1.x, f1.y);
                ev2[ch*4+2] = packf2(f2.x, f2.y);
                ev2[ch*4+3] = packf2(f3.x, f3.y);
            }
            unsigned long long spk = 0ULL;
#pragma unroll
            for (int v = 0; v < 8; v++) fma2(spk, ev2[v], cv2[v]);
            float2 sp2 = unpack2(spk);
            float s = sp2.x + sp2.y;
#pragma unroll
            for (int off = 16; off > 0; off >>= 1)
                s += __shfl_xor_sync(0xFFFFFFFFu, s, off);
            float r = (s > 0.0f) ? 1.0f/s : 0.0f;
            if (iter == 3) {
                if (lane == 0) g_r[slice*GD + i] = r;
                uint4* gp = (uint4*)(g_E + (size_t)slice*GD*GP + (size_t)i*GP);
                gp[lane]      = raws[0];
                gp[32 + lane] = raws[1];
            }
            unsigned long long r2 = pack2(r);
#pragma unroll
            for (int v = 0; v < 8; v++) fma2(colacc2[v], r2, ev2[v]);
        }
        // strip writes: pair v covers cols c0, c0+1
#pragma unroll
        for (int v = 0; v < 8; v++) {
            int c0 = (v >> 2)*256 + lane*8 + (v & 3)*2;
            float2 ca = unpack2(colacc2[v]);
            strip[w*544 + SIDX(c0)]   = ca.x;
            strip[w*544 + SIDX(c0+1)] = ca.y;
        }
        __syncthreads();
        {
            int cc = tid;
            float s2 = 0.0f;
#pragma unroll
            for (int ww = 0; ww < 16; ww++) s2 += strip[ww*544 + SIDX(cc)];
            float rec = (s2 > 0.0f) ? 1.0f/s2 : 0.0f;
            if (iter == 3) g_c[slice*GP + cc] = rec;
            else           strip[SIDX(cc)] = rec;
        }
        __syncthreads();
        if (iter < 3) {
#pragma unroll
            for (int v = 0; v < 8; v++) {
                int c0 = (v >> 2)*256 + lane*8 + (v & 3)*2;
                cv2[v] = packf2(strip[SIDX(c0)], strip[SIDX(c0+1)]);
            }
            __syncthreads();
        }
    }
}

// ---------------- write a_dp = diag(r) E diag(c), conflict-free staging ----------
#define CSTR 516
__global__ __launch_bounds__(256) void k_adp(float* __restrict__ out) {
    __shared__ float shEf[8*CSTR];
    __shared__ float cshr[8*CSTR];
    __shared__ float rsh[8];
    int b = blockIdx.x;
    int n = b >> 7, i = b & 127;
    int tid = threadIdx.x;

    if (tid < 8) rsh[tid] = g_r[(n*8 + tid)*GD + i];
#pragma unroll
    for (int t = 0; t < 2; t++) {
        int f = t*256 + tid;
        int h = f >> 6, qq = f & 63;
        uint4 raw = ((const uint4*)(g_E + ((size_t)(n*8 + h)*GD + i)*GP))[qq];
        float2 f0 = __half22float2(*(__half2*)&raw.x);
        float2 f1 = __half22float2(*(__half2*)&raw.y);
        float2 f2 = __half22float2(*(__half2*)&raw.z);
        float2 f3 = __half22float2(*(__half2*)&raw.w);
        float* dstE = &shEf[h*CSTR + qq*8];
        ((float4*)dstE)[0] = make_float4(f0.x, f0.y, f1.x, f1.y);
        ((float4*)dstE)[1] = make_float4(f2.x, f2.y, f3.x, f3.y);
    }
#pragma unroll
    for (int t = 0; t < 4; t++) {
        int f = t*256 + tid;
        int h = f >> 7, j4 = f & 127;
        ((float4*)&cshr[h*CSTR])[j4] =
            ((const float4*)(g_c + (size_t)(n*8 + h)*GP))[j4];
    }
    __syncthreads();

    float* dst = out + (size_t)b * GP * 8;
#pragma unroll
    for (int t = 0; t < 16; t++) {
        int o = t*256 + tid;
        int j = o >> 3, h = o & 7;
        dst[o] = rsh[h] * shEf[h*CSTR + j] * cshr[h*CSTR + j];
    }
}

// ---------------- launch -----------------------------------------------------------
extern "C" void kernel_launch(void* const* d_in, const int* in_sizes, int n_in,
                              void* d_out, int out_size) {
    const float* protein = (const float*)d_in[0];
    const float* drug    = (const float*)d_in[1];
    const void*  maskp   = d_in[2];
    const void*  maskd   = d_in[3];
    const float* Wk_p    = (const float*)d_in[5];
    const float* Wv_p    = (const float*)d_in[6];
    const float* Wq_d    = (const float*)d_in[7];
    const float* Wv_d    = (const float*)d_in[9];
    float* out = (float*)d_out;

    size_t adp_elems = (size_t)NB * GD * GP * HN;
    int  write_q   = (((size_t)out_size > adp_elems) || ((size_t)out_size < adp_elems)) ? 1 : 0;
    bool write_adp = ((size_t)out_size >= adp_elems);
    size_t adp_off = ((size_t)out_size >= adp_elems + NB*512) ? (size_t)NB*512 : 0;

    static int smem_set = 0;
    if (!smem_set) {
        cudaFuncSetAttribute(k_mega, cudaFuncAttributeMaxDynamicSharedMemorySize, SM_TOT);
        smem_set = 1;
    }

    k_group2<<<NB*GP + NB*GD, 256>>>(protein, drug, maskp, maskd);
    k_fuse1<<<768, 256>>>(Wk_p, Wq_d);
    k_mega<<<NHS + NB, 512, SM_TOT>>>(Wv_p, Wv_d, out, write_q);
    if (write_adp) {
        k_adp<<<NB*GD, 256>>>(out + adp_off);
    }
}

// round 16
// speedup vs baseline: 1.4485x; 1.1074x over previous
#include <cuda_runtime.h>
#include <cuda_fp16.h>
#include <cstdint>

// ---------------- problem constants ----------------
#define NB  16
#define HN  8
#define HDM 32
#define DM  256
#define GP  512
#define GD  128
#define NHS 128          // NB*HN slices
#define SEG 16
// (1/sqrt(32)) * log2(e)
#define EXPSC 0.2550526808750678f

// swizzled smem index: conflict-free for sink strip pattern
#define SIDX(c) ((((c) & 31) * 17) + ((c) >> 5))

// mega-kernel shared memory layout (bytes)
#define ESTR   520
#define SM_E   0
#define SM_QK  133120
#define SM_MR  168192
#define SM_MC  168704
#define SM_TOT 170752

// fuse1 proj dynamic smem: 2 buffers x (A 128x36 + B 128x36) floats
#define TSTR   36
#define TILEF  (128*TSTR)                // 4608 floats per tile
#define FS_TOT (4*TILEF*4)               // 73728 bytes

// ---------------- scratch (static device globals; no runtime alloc) ------------
__device__ float  g_pg[NB*GP*DM];
__device__ float  g_dg[NB*GD*DM];
__device__ float  g_mp[NB*GP];
__device__ float  g_md[NB*GD];
__device__ float  g_part[2*NB*SEG*DM];
__device__ float  g_cpart[2*NB*SEG];
__device__ float  g_kp[NHS*GP*HDM];
__device__ float  g_qd[NHS*GD*HDM];
__device__ __half g_E [NHS*GD*GP];
__device__ float  g_r [NHS*GD];
__device__ float  g_c [NHS*GP];

// ---------------- helpers ----------------------------------------------------------
__device__ __forceinline__ unsigned long long pack2(float x) {
    unsigned long long r;
    asm("mov.b64 %0, {%1, %1};" : "=l"(r) : "r"(__float_as_uint(x)));
    return r;
}
__device__ __forceinline__ unsigned long long packf2(float lo, float hi) {
    unsigned long long r;
    asm("mov.b64 %0, {%1, %2};" : "=l"(r) : "f"(lo), "f"(hi));
    return r;
}
__device__ __forceinline__ void fma2(unsigned long long& d,
                                     unsigned long long a, unsigned long long b) {
    asm("fma.rn.f32x2 %0, %1, %2, %0;" : "+l"(d) : "l"(a), "l"(b));
}
__device__ __forceinline__ float2 unpack2(unsigned long long v) {
    unsigned lo, hi;
    asm("mov.b64 {%0, %1}, %2;" : "=r"(lo), "=r"(hi) : "l"(v));
    return make_float2(__uint_as_float(lo), __uint_as_float(hi));
}
__device__ __forceinline__ uint32_t tf32cvt(float x) {
    uint32_t r;
    asm("cvt.rna.tf32.f32 %0, %1;" : "=r"(r) : "f"(x));
    return r;
}
__device__ __forceinline__ void mma_tf32(float& c0, float& c1, float& c2, float& c3,
                                         uint32_t a0, uint32_t a1, uint32_t a2, uint32_t a3,
                                         uint32_t b0, uint32_t b1) {
    asm volatile(
        "mma.sync.aligned.m16n8k8.row.col.f32.tf32.tf32.f32 "
        "{%0,%1,%2,%3}, {%4,%5,%6,%7}, {%8,%9}, {%0,%1,%2,%3};"
        : "+f"(c0), "+f"(c1), "+f"(c2), "+f"(c3)
        : "r"(a0), "r"(a1), "r"(a2), "r"(a3), "r"(b0), "r"(b1));
}
__device__ __forceinline__ uint32_t ex2_f16x2(uint32_t x) {
    uint32_t r;
    asm("ex2.approx.f16x2 %0, %1;" : "=r"(r) : "r"(x));
    return r;
}
__device__ __forceinline__ uint32_t smem_u32(const void* p) {
    uint32_t a;
    asm("{ .reg .u64 t; cvta.to.shared.u64 t, %1; cvt.u32.u64 %0, t; }"
        : "=r"(a) : "l"(p));
    return a;
}
__device__ __forceinline__ void cp_async16(uint32_t dst, const void* src) {
    asm volatile("cp.async.ca.shared.global [%0], [%1], 16;"
                 :: "r"(dst), "l"(src) : "memory");
}
#define CP_COMMIT() asm volatile("cp.async.commit_group;" ::: "memory")
template<int N> __device__ __forceinline__ void cp_wait() {
    asm volatile("cp.async.wait_group %0;" :: "n"(N) : "memory");
}

__device__ __forceinline__ float mask_at(const void* M, int tok, int mode) {
    switch (mode) {
        case 0:  return ((const float*)M)[tok] != 0.0f ? 1.0f : 0.0f;
        case 1:  return ((const int*)M)[tok]   != 0    ? 1.0f : 0.0f;
        case 2:  return ((const unsigned char*)M)[tok] ? 1.0f : 0.0f;
        default: return ((const unsigned short*)M)[tok] ? 1.0f : 0.0f;
    }
}

// ---------------- grouping (with inline per-block mask-dtype probe) ----------------
__global__ void k_group2(const float* __restrict__ P, const float* __restrict__ Dr,
                         const void* __restrict__ MP, const void* __restrict__ MD) {
    __shared__ int cnt[4];
    int d = threadIdx.x;
    if (d < 4) cnt[d] = 0;
    __syncthreads();
    {
        unsigned wmk = ((const unsigned int*)MP)[d];
        if (wmk == 0x3F803F80u || wmk == 0x3C003C00u) atomicAdd(&cnt[0], 1);
        if (wmk == 0x3F800000u)                       atomicAdd(&cnt[1], 1);
        if (wmk > 1u)                                 atomicAdd(&cnt[2], 1);
    }
    __syncthreads();

    int b = blockIdx.x;
    const float* X; const void* M; float* out; float* mout;
    if (b < NB*GP) { X = P;  M = MP; out = g_pg; mout = g_mp; }
    else           { b -= NB*GP; X = Dr; M = MD; out = g_dg; mout = g_md; }
    const float* src = X + (size_t)b * 4 * DM;
    out[(size_t)b * DM + d] =
        0.25f * (src[d] + src[DM + d] + src[2*DM + d] + src[3*DM + d]);
    if (d == 0) {
        int mode;
        if (cnt[0] >= 4)      mode = 3;
        else if (cnt[1] >= 4) mode = 0;
        else if (cnt[2] > 0)  mode = 2;
        else                  mode = 1;
        float m = mask_at(M, 4*b+0, mode) + mask_at(M, 4*b+1, mode)
                + mask_at(M, 4*b+2, mode) + mask_at(M, 4*b+3, mode);
        mout[b] = (m > 0.0f) ? 1.0f : 0.0f;
    }
}

// ---------------- fused launch 1: masked-sum partials + cp.async proj GEMM --------
// blocks [0,512): msum;  [512,768): proj (double-buffered cp.async, raw-f32 tf32)
__global__ __launch_bounds__(256) void k_fuse1(const float* __restrict__ Wkp,
                                               const float* __restrict__ Wqd) {
    extern __shared__ float dsm[];
    int tid = threadIdx.x;

    if (blockIdx.x < 512) {
        int s = blockIdx.x;
        int n = s & 15, ent = (s >> 4) & 1, seg = s >> 5;
        int d = tid;
        const float* X = ent ? g_dg : g_pg;
        const float* m = ent ? g_md : g_mp;
        int G = ent ? GD : GP;
        int chunk = G / SEG;
        int g0 = seg * chunk;
        float a0 = 0.f, a1 = 0.f, a2 = 0.f, a3 = 0.f;
        for (int g = g0; g < g0 + chunk; g += 4) {
            a0 += m[n*G+g+0] * X[((size_t)(n*G+g+0))*DM + d];
            a1 += m[n*G+g+1] * X[((size_t)(n*G+g+1))*DM + d];
            a2 += m[n*G+g+2] * X[((size_t)(n*G+g+2))*DM + d];
            a3 += m[n*G+g+3] * X[((size_t)(n*G+g+3))*DM + d];
        }
        g_part[((ent*NB + n)*SEG + seg)*DM + d] = (a0 + a1) + (a2 + a3);
        if (d == 0) {
            float c = 0.0f;
            for (int g = g0; g < g0 + chunk; g++) c += m[n*G + g];
            g_cpart[(ent*NB + n)*SEG + seg] = c;
        }
        return;
    }
    int pb = blockIdx.x - 512;
    int bx = pb & 63, by = (pb >> 6) & 1, bz = pb >> 7;
    const float* X; const float* W; float* OUT; int L;
    if (bz == 0) { X = g_pg; W = Wkp; OUT = g_kp; L = GP; }
    else         { if (bx >= 16) return;
                   X = g_dg; W = Wqd; OUT = g_qd; L = GD; }

    float* As = dsm;               // [2][128*TSTR] row-major raw f32
    float* Bs = dsm + 2*TILEF;     // [2][128*TSTR]
    uint32_t as_base = smem_u32(As);
    uint32_t bs_base = smem_u32(Bs);

    int lane = tid & 31, w = tid >> 5;
    int g = lane >> 2, tk = lane & 3;
    int wm = (w & 3) * 32, wn = (w >> 2) * 64;
    int m0 = bx * 128, o0 = by * 128;

    // fill coordinates: 4 chunks (16B) per thread per matrix
    int frow[4], fch[4];
    uint32_t aoff[4], boff[4];
#pragma unroll
    for (int s = 0; s < 4; s++) {
        int f = tid + s*256;           // 0..1023
        frow[s] = f >> 3; fch[s] = f & 7;
        uint32_t byteoff = (uint32_t)(frow[s]*TSTR + fch[s]*4) * 4u;
        aoff[s] = as_base + byteoff;
        boff[s] = bs_base + byteoff;
    }

    float c[2][8][4];
#pragma unroll
    for (int mi = 0; mi < 2; mi++)
#pragma unroll
        for (int ni = 0; ni < 8; ni++)
#pragma unroll
            for (int r = 0; r < 4; r++) c[mi][ni][r] = 0.0f;

    // prologue fill: tile 0 into buffer 0
#pragma unroll
    for (int s = 0; s < 4; s++) {
        cp_async16(aoff[s], &X[(size_t)(m0+frow[s])*256 + fch[s]*4]);
        cp_async16(boff[s], &W[(size_t)(o0+frow[s])*256 + fch[s]*4]);
    }
    CP_COMMIT();

    const uint32_t bufbytes = (uint32_t)TILEF * 4u;
    for (int kt = 0; kt < 8; kt++) {
        int buf = kt & 1;
        if (kt < 7) {
            uint32_t nboff = (uint32_t)(buf ^ 1) * bufbytes;
            int k0 = (kt + 1) * 32;
#pragma unroll
            for (int s = 0; s < 4; s++) {
                cp_async16(aoff[s] + nboff, &X[(size_t)(m0+frow[s])*256 + k0 + fch[s]*4]);
                cp_async16(boff[s] + nboff, &W[(size_t)(o0+frow[s])*256 + k0 + fch[s]*4]);
            }
            CP_COMMIT();
            cp_wait<1>();
        } else {
            cp_wait<0>();
        }
        __syncthreads();

        const uint32_t* Ab = (const uint32_t*)(As + buf*TILEF);
        const uint32_t* Bb = (const uint32_t*)(Bs + buf*TILEF);
#pragma unroll
        for (int kh = 0; kh < 4; kh++) {
            int kb = kh*8;
            uint32_t aH[2][4];
#pragma unroll
            for (int mi = 0; mi < 2; mi++) {
                int rb = wm + mi*16 + g;
                aH[mi][0] = Ab[rb*TSTR     + kb+tk  ];
                aH[mi][1] = Ab[(rb+8)*TSTR + kb+tk  ];
                aH[mi][2] = Ab[rb*TSTR     + kb+tk+4];
                aH[mi][3] = Ab[(rb+8)*TSTR + kb+tk+4];
            }
            uint32_t bH[8][2];
#pragma unroll
            for (int ni = 0; ni < 8; ni++) {
                int nb2 = wn + ni*8 + g;
                bH[ni][0] = Bb[nb2*TSTR + kb+tk  ];
                bH[ni][1] = Bb[nb2*TSTR + kb+tk+4];
            }
#pragma unroll
            for (int mi = 0; mi < 2; mi++)
#pragma unroll
                for (int ni = 0; ni < 8; ni++) {
                    float* cc = c[mi][ni];
                    mma_tf32(cc[0],cc[1],cc[2],cc[3],
                             aH[mi][0],aH[mi][1],aH[mi][2],aH[mi][3],
                             bH[ni][0],bH[ni][1]);
                }
        }
        __syncthreads();
    }

#pragma unroll
    for (int mi = 0; mi < 2; mi++)
#pragma unroll
        for (int ni = 0; ni < 8; ni++) {
            int o = o0 + wn + ni*8 + 2*tk;
            int h = o >> 5, dd = o & 31;
            int m = m0 + wm + mi*16 + g;
            int nb = m / L, gg = m % L;
            float* dst = &OUT[(((size_t)(nb*HN + h))*L + gg)*HDM + dd];
            *(float2*)dst = make_float2(c[mi][ni][0], c[mi][ni][1]);
            int m2 = m + 8;
            int nb2 = m2 / L, gg2 = m2 % L;
            float* dst2 = &OUT[(((size_t)(nb2*HN + h))*L + gg2)*HDM + dd];
            *(float2*)dst2 = make_float2(c[mi][ni][2], c[mi][ni][3]);
        }
}

// ---------------- mega kernel: logits (TF32 MMA) + 4x Sinkhorn, E in smem ---------
#define ASTR 137
__global__ __launch_bounds__(512) void k_mega(const float* __restrict__ Wvp,
                                              const float* __restrict__ Wvd,
                                              float* __restrict__ qout, int do_q) {
    extern __shared__ char smem[];
    int tid = threadIdx.x;
    int lane = tid & 31, w = tid >> 5;

    if (blockIdx.x >= NHS) {
        if (!do_q) return;
        float* sp   = (float*)smem;
        float* sd   = sp + DM;
        float* cnts = sd + DM;
        int n = blockIdx.x - NHS;
        if (tid < DM) {
            float accp = 0.0f, accd = 0.0f;
#pragma unroll
            for (int s = 0; s < SEG; s++) {
                accp += g_part[((0*NB + n)*SEG + s)*DM + tid];
                accd += g_part[((1*NB + n)*SEG + s)*DM + tid];
            }
            sp[tid] = accp; sd[tid] = accd;
        }
        if (tid < 2) {
            float c = 0.0f;
#pragma unroll
            for (int s = 0; s < SEG; s++) c += g_cpart[(tid*NB + n)*SEG + s];
            cnts[tid] = c;
        }
        __syncthreads();
        float cp = cnts[0], cd = cnts[1];
        for (int o = w; o < DM; o += 16) {
            float acc = 0.0f;
#pragma unroll
            for (int t = 0; t < 8; t++) {
                int k = lane + t*32;
                acc += sp[k]*Wvp[(size_t)o*DM + k] + sd[k]*Wvd[(size_t)o*DM + k];
            }
#pragma unroll
            for (int off = 16; off > 0; off >>= 1)
                acc += __shfl_xor_sync(0xFFFFFFFFu, acc, off);
            if (lane == 0) {
                qout[(size_t)n*512 + o]       = 0.5f * acc / cp;
                qout[(size_t)n*512 + 256 + o] = 0.5f * acc / cd;
            }
        }
        return;
    }

    int slice = blockIdx.x;
    int n = slice >> 3;
    const float* q = g_qd + (size_t)slice * GD * HDM;
    const float* k = g_kp + (size_t)slice * GP * HDM;

    __half*   Esm   = (__half*)(smem + SM_E);
    uint32_t* Qs    = (uint32_t*)(smem + SM_QK);
    uint32_t* Ks    = Qs + 32*ASTR;
    float*    strip = (float*)(smem + SM_QK);
    float*    mrb   = (float*)(smem + SM_MR);
    float*    mcb   = (float*)(smem + SM_MC);

    int g = lane >> 2, tk = lane & 3;
    int wm = (w & 3) * 32, wn = (w >> 2) * 32;

#pragma unroll
    for (int s = 0; s < 2; s++) {
        int f = tid + s*512;
        int row = f >> 3, c4 = f & 7;
        float4 v = *(const float4*)&q[(size_t)row*HDM + c4*4];
        Qs[(c4*4+0)*ASTR + row] = tf32cvt(v.x);
        Qs[(c4*4+1)*ASTR + row] = tf32cvt(v.y);
        Qs[(c4*4+2)*ASTR + row] = tf32cvt(v.z);
        Qs[(c4*4+3)*ASTR + row] = tf32cvt(v.w);
    }
    if (tid < 128) mrb[tid] = (g_md[n*GD + tid] > 0.0f) ? 0.0f : -10000.0f;
    mcb[tid] = (g_mp[n*GP + tid] > 0.0f) ? 0.0f : -10000.0f;

    for (int jt = 0; jt < 4; jt++) {
        int j0 = jt * 128;
#pragma unroll
        for (int s = 0; s < 2; s++) {
            int f = tid + s*512;
            int row = f >> 3, c4 = f & 7;
            float4 v = *(const float4*)&k[(size_t)(j0+row)*HDM + c4*4];
            Ks[(c4*4+0)*ASTR + row] = tf32cvt(v.x);
            Ks[(c4*4+1)*ASTR + row] = tf32cvt(v.y);
            Ks[(c4*4+2)*ASTR + row] = tf32cvt(v.z);
            Ks[(c4*4+3)*ASTR + row] = tf32cvt(v.w);
        }
        __syncthreads();

        float c[2][4][4];
#pragma unroll
        for (int mi = 0; mi < 2; mi++)
#pragma unroll
            for (int ni = 0; ni < 4; ni++)
#pragma unroll
                for (int r = 0; r < 4; r++) c[mi][ni][r] = 0.0f;

#pragma unroll
        for (int kh = 0; kh < 4; kh++) {
            int kb = kh*8;
            uint32_t aH[2][4];
#pragma unroll
            for (int mi = 0; mi < 2; mi++) {
                int rb = wm + mi*16 + g;
                aH[mi][0] = Qs[(kb+tk  )*ASTR + rb];
                aH[mi][1] = Qs[(kb+tk  )*ASTR + rb + 8];
                aH[mi][2] = Qs[(kb+tk+4)*ASTR + rb];
                aH[mi][3] = Qs[(kb+tk+4)*ASTR + rb + 8];
            }
            uint32_t bH[4][2];
#pragma unroll
            for (int ni = 0; ni < 4; ni++) {
                int nb = wn + ni*8 + g;
                bH[ni][0] = Ks[(kb+tk  )*ASTR + nb];
                bH[ni][1] = Ks[(kb+tk+4)*ASTR + nb];
            }
#pragma unroll
            for (int mi = 0; mi < 2; mi++)
#pragma unroll
                for (int ni = 0; ni < 4; ni++) {
                    float* cc = c[mi][ni];
                    mma_tf32(cc[0],cc[1],cc[2],cc[3],
                             aH[mi][0],aH[mi][1],aH[mi][2],aH[mi][3],
                             bH[ni][0],bH[ni][1]);
                }
        }

#pragma unroll
        for (int mi = 0; mi < 2; mi++) {
            int row1 = wm + mi*16 + g;
            int row2 = row1 + 8;
            float br1 = mrb[row1], br2 = mrb[row2];
#pragma unroll
            for (int ni = 0; ni < 4; ni++) {
                int o  = wn + ni*8 + 2*tk;
                int oc = j0 + o;
                float bc0 = mcb[oc], bc1 = mcb[oc+1];
                float* cc = c[mi][ni];
                __half2 xa = __floats2half2_rn(fmaf(cc[0], EXPSC, br1 + bc0),
                                               fmaf(cc[1], EXPSC, br1 + bc1));
                *(uint32_t*)&Esm[row1*ESTR + oc] = ex2_f16x2(*(uint32_t*)&xa);
                __half2 xb = __floats2half2_rn(fmaf(cc[2], EXPSC, br2 + bc0),
                                               fmaf(cc[3], EXPSC, br2 + bc1));
                *(uint32_t*)&Esm[row2*ESTR + oc] = ex2_f16x2(*(uint32_t*)&xb);
            }
        }
        __syncthreads();
    }

    unsigned long long cv2[8];
#pragma unroll
    for (int v = 0; v < 8; v++) cv2[v] = pack2(1.0f);

    for (int iter = 0; iter < 4; iter++) {
        unsigned long long colacc2[8];
#pragma unroll
        for (int v = 0; v < 8; v++) colacc2[v] = 0ULL;

#pragma unroll
        for (int ridx = 0; ridx < 8; ridx++) {
            int i = w + ridx*16;
            const uint4* rp = (const uint4*)(Esm + (size_t)i * ESTR);
            uint4 raws[2];
            unsigned long long ev2[8];
#pragma unroll
            for (int ch = 0; ch < 2; ch++) {
                uint4 raw = rp[ch*32 + lane];
                raws[ch] = raw;
                float2 f0 = __half22float2(*(__half2*)&raw.x);
                float2 f1 = __half22float2(*(__half2*)&raw.y);
                float2 f2 = __half22float2(*(__half2*)&raw.z);
                float2 f3 = __half22float2(*(__half2*)&raw.w);
                ev2[ch*4+0] = packf2(f0.x, f0.y);
                ev2[ch*4+1] = packf2(f1.x, f1.y);
                ev2[ch*4+2] = packf2(f2.x, f2.y);
                ev2[ch*4+3] = packf2(f3.x, f3.y);
            }
            unsigned long long spk = 0ULL;
#pragma unroll
            for (int v = 0; v < 8; v++) fma2(spk, ev2[v], cv2[v]);
            float2 sp2 = unpack2(spk);
            float s = sp2.x + sp2.y;
#pragma unroll
            for (int off = 16; off > 0; off >>= 1)
                s += __shfl_xor_sync(0xFFFFFFFFu, s, off);
            float r = (s > 0.0f) ? 1.0f/s : 0.0f;
            if (iter == 3) {
                if (lane == 0) g_r[slice*GD + i] = r;
                uint4* gp = (uint4*)(g_E + (size_t)slice*GD*GP + (size_t)i*GP);
                gp[lane]      = raws[0];
                gp[32 + lane] = raws[1];
            }
            unsigned long long r2 = pack2(r);
#pragma unroll
            for (int v = 0; v < 8; v++) fma2(colacc2[v], r2, ev2[v]);
        }
#pragma unroll
        for (int v = 0; v < 8; v++) {
            int c0 = (v >> 2)*256 + lane*8 + (v & 3)*2;
            float2 ca = unpack2(colacc2[v]);
            strip[w*544 + SIDX(c0)]   = ca.x;
            strip[w*544 + SIDX(c0+1)] = ca.y;
        }
        __syncthreads();
        {
            int cc = tid;
            float s2 = 0.0f;
#pragma unroll
            for (int ww = 0; ww < 16; ww++) s2 += strip[ww*544 + SIDX(cc)];
            float rec = (s2 > 0.0f) ? 1.0f/s2 : 0.0f;
            if (iter == 3) g_c[slice*GP + cc] = rec;
            else           strip[SIDX(cc)] = rec;
        }
        __syncthreads();
        if (iter < 3) {
#pragma unroll
            for (int v = 0; v < 8; v++) {
                int c0 = (v >> 2)*256 + lane*8 + (v & 3)*2;
                cv2[v] = packf2(strip[SIDX(c0)], strip[SIDX(c0+1)]);
            }
            __syncthreads();
        }
    }
}

// ---------------- write a_dp = diag(r) E diag(c), vectorized stores ---------------
#define CSTR 516
__global__ __launch_bounds__(256) void k_adp(float* __restrict__ out) {
    __shared__ float shEf[8*CSTR];
    __shared__ float cshr[8*CSTR];
    __shared__ float rsh[8];
    int b = blockIdx.x;
    int n = b >> 7, i = b & 127;
    int tid = threadIdx.x;

    if (tid < 8) rsh[tid] = g_r[(n*8 + tid)*GD + i];
#pragma unroll
    for (int t = 0; t < 2; t++) {
        int f = t*256 + tid;
        int h = f >> 6, qq = f & 63;
        uint4 raw = ((const uint4*)(g_E + ((size_t)(n*8 + h)*GD + i)*GP))[qq];
        float2 f0 = __half22float2(*(__half2*)&raw.x);
        float2 f1 = __half22float2(*(__half2*)&raw.y);
        float2 f2 = __half22float2(*(__half2*)&raw.z);
        float2 f3 = __half22float2(*(__half2*)&raw.w);
        float* dstE = &shEf[h*CSTR + qq*8];
        ((float4*)dstE)[0] = make_float4(f0.x, f0.y, f1.x, f1.y);
        ((float4*)dstE)[1] = make_float4(f2.x, f2.y, f3.x, f3.y);
    }
#pragma unroll
    for (int t = 0; t < 4; t++) {
        int f = t*256 + tid;
        int h = f >> 7, j4 = f & 127;
        ((float4*)&cshr[h*CSTR])[j4] =
            ((const float4*)(g_c + (size_t)(n*8 + h)*GP))[j4];
    }
    __syncthreads();

    float* dst = out + (size_t)b * GP * 8;
#pragma unroll
    for (int t = 0; t < 4; t++) {
        int o = t*1024 + tid*4;
        int j = o >> 3, h0 = o & 7;     // h0 in {0,4}
        float4 v;
        v.x = rsh[h0+0] * shEf[(h0+0)*CSTR + j] * cshr[(h0+0)*CSTR + j];
        v.y = rsh[h0+1] * shEf[(h0+1)*CSTR + j] * cshr[(h0+1)*CSTR + j];
        v.z = rsh[h0+2] * shEf[(h0+2)*CSTR + j] * cshr[(h0+2)*CSTR + j];
        v.w = rsh[h0+3] * shEf[(h0+3)*CSTR + j] * cshr[(h0+3)*CSTR + j];
        *(float4*)&dst[o] = v;
    }
}

// ---------------- launch -----------------------------------------------------------
extern "C" void kernel_launch(void* const* d_in, const int* in_sizes, int n_in,
                              void* d_out, int out_size) {
    const float* protein = (const float*)d_in[0];
    const float* drug    = (const float*)d_in[1];
    const void*  maskp   = d_in[2];
    const void*  maskd   = d_in[3];
    const float* Wk_p    = (const float*)d_in[5];
    const float* Wv_p    = (const float*)d_in[6];
    const float* Wq_d    = (const float*)d_in[7];
    const float* Wv_d    = (const float*)d_in[9];
    float* out = (float*)d_out;

    size_t adp_elems = (size_t)NB * GD * GP * HN;
    int  write_q   = (((size_t)out_size > adp_elems) || ((size_t)out_size < adp_elems)) ? 1 : 0;
    bool write_adp = ((size_t)out_size >= adp_elems);
    size_t adp_off = ((size_t)out_size >= adp_elems + NB*512) ? (size_t)NB*512 : 0;

    static int smem_set = 0;
    if (!smem_set) {
        cudaFuncSetAttribute(k_mega,  cudaFuncAttributeMaxDynamicSharedMemorySize, SM_TOT);
        cudaFuncSetAttribute(k_fuse1, cudaFuncAttributeMaxDynamicSharedMemorySize, FS_TOT);
        smem_set = 1;
    }

    k_group2<<<NB*GP + NB*GD, 256>>>(protein, drug, maskp, maskd);
    k_fuse1<<<768, 256, FS_TOT>>>(Wk_p, Wq_d);
    k_mega<<<NHS + NB, 512, SM_TOT>>>(Wv_p, Wv_d, out, write_q);
    if (write_adp) {
        k_adp<<<NB*GD, 256>>>(out + adp_off);
    }
}

// round 17
// speedup vs baseline: 1.4924x; 1.0303x over previous
#include <cuda_runtime.h>
#include <cuda_fp16.h>
#include <cstdint>

// ---------------- problem constants ----------------
#define NB  16
#define HN  8
#define HDM 32
#define DM  256
#define GP  512
#define GD  128
#define NHS 128          // NB*HN slices
#define SEG 16
// (1/sqrt(32)) * log2(e)
#define EXPSC 0.2550526808750678f

// swizzled smem index: conflict-free for sink strip pattern
#define SIDX(c) ((((c) & 31) * 17) + ((c) >> 5))

// mega-kernel shared memory layout (bytes)
#define ESTR   520
#define SM_E   0                          // 128*520*2 = 133120
#define SM_Q   133120                     // 32*137*4  = 17536
#define SM_K   150656                     // 2*128*36*4 = 36864 (double-buffered raw f32)
#define SM_MR  187520                     // float[128]
#define SM_MC  188032                     // float[512]
#define SM_TOT 190080
#define KSTR2  36
#define KBUF   (128*KSTR2)                // floats per K buffer

// fuse1 proj dynamic smem: 2 buffers x (A 128x36 + B 128x36) floats
#define TSTR   36
#define TILEF  (128*TSTR)
#define FS_TOT (4*TILEF*4)

// ---------------- scratch (static device globals; no runtime alloc) ------------
__device__ float  g_pg[NB*GP*DM];
__device__ float  g_dg[NB*GD*DM];
__device__ float  g_mp[NB*GP];
__device__ float  g_md[NB*GD];
__device__ float  g_part[2*NB*SEG*DM];
__device__ float  g_cpart[2*NB*SEG];
__device__ float  g_kp[NHS*GP*HDM];
__device__ float  g_qd[NHS*GD*HDM];
__device__ __half g_E [NHS*GD*GP];
__device__ float  g_r [NHS*GD];
__device__ float  g_c [NHS*GP];

// ---------------- helpers ----------------------------------------------------------
__device__ __forceinline__ unsigned long long pack2(float x) {
    unsigned long long r;
    asm("mov.b64 %0, {%1, %1};" : "=l"(r) : "r"(__float_as_uint(x)));
    return r;
}
__device__ __forceinline__ unsigned long long packf2(float lo, float hi) {
    unsigned long long r;
    asm("mov.b64 %0, {%1, %2};" : "=l"(r) : "f"(lo), "f"(hi));
    return r;
}
__device__ __forceinline__ void fma2(unsigned long long& d,
                                     unsigned long long a, unsigned long long b) {
    asm("fma.rn.f32x2 %0, %1, %2, %0;" : "+l"(d) : "l"(a), "l"(b));
}
__device__ __forceinline__ float2 unpack2(unsigned long long v) {
    unsigned lo, hi;
    asm("mov.b64 {%0, %1}, %2;" : "=r"(lo), "=r"(hi) : "l"(v));
    return make_float2(__uint_as_float(lo), __uint_as_float(hi));
}
__device__ __forceinline__ uint32_t tf32cvt(float x) {
    uint32_t r;
    asm("cvt.rna.tf32.f32 %0, %1;" : "=r"(r) : "f"(x));
    return r;
}
__device__ __forceinline__ void mma_tf32(float& c0, float& c1, float& c2, float& c3,
                                         uint32_t a0, uint32_t a1, uint32_t a2, uint32_t a3,
                                         uint32_t b0, uint32_t b1) {
    asm volatile(
        "mma.sync.aligned.m16n8k8.row.col.f32.tf32.tf32.f32 "
        "{%0,%1,%2,%3}, {%4,%5,%6,%7}, {%8,%9}, {%0,%1,%2,%3};"
        : "+f"(c0), "+f"(c1), "+f"(c2), "+f"(c3)
        : "r"(a0), "r"(a1), "r"(a2), "r"(a3), "r"(b0), "r"(b1));
}
__device__ __forceinline__ uint32_t ex2_f16x2(uint32_t x) {
    uint32_t r;
    asm("ex2.approx.f16x2 %0, %1;" : "=r"(r) : "r"(x));
    return r;
}
__device__ __forceinline__ uint32_t smem_u32(const void* p) {
    uint32_t a;
    asm("{ .reg .u64 t; cvta.to.shared.u64 t, %1; cvt.u32.u64 %0, t; }"
        : "=r"(a) : "l"(p));
    return a;
}
__device__ __forceinline__ void cp_async16(uint32_t dst, const void* src) {
    asm volatile("cp.async.ca.shared.global [%0], [%1], 16;"
                 :: "r"(dst), "l"(src) : "memory");
}
#define CP_COMMIT() asm volatile("cp.async.commit_group;" ::: "memory")
template<int N> __device__ __forceinline__ void cp_wait() {
    asm volatile("cp.async.wait_group %0;" :: "n"(N) : "memory");
}

__device__ __forceinline__ float mask_at(const void* M, int tok, int mode) {
    switch (mode) {
        case 0:  return ((const float*)M)[tok] != 0.0f ? 1.0f : 0.0f;
        case 1:  return ((const int*)M)[tok]   != 0    ? 1.0f : 0.0f;
        case 2:  return ((const unsigned char*)M)[tok] ? 1.0f : 0.0f;
        default: return ((const unsigned short*)M)[tok] ? 1.0f : 0.0f;
    }
}

// ---------------- grouping (with inline per-block mask-dtype probe) ----------------
__global__ void k_group2(const float* __restrict__ P, const float* __restrict__ Dr,
                         const void* __restrict__ MP, const void* __restrict__ MD) {
    __shared__ int cnt[4];
    int d = threadIdx.x;
    if (d < 4) cnt[d] = 0;
    __syncthreads();
    {
        unsigned wmk = ((const unsigned int*)MP)[d];
        if (wmk == 0x3F803F80u || wmk == 0x3C003C00u) atomicAdd(&cnt[0], 1);
        if (wmk == 0x3F800000u)                       atomicAdd(&cnt[1], 1);
        if (wmk > 1u)                                 atomicAdd(&cnt[2], 1);
    }
    __syncthreads();

    int b = blockIdx.x;
    const float* X; const void* M; float* out; float* mout;
    if (b < NB*GP) { X = P;  M = MP; out = g_pg; mout = g_mp; }
    else           { b -= NB*GP; X = Dr; M = MD; out = g_dg; mout = g_md; }
    const float* src = X + (size_t)b * 4 * DM;
    out[(size_t)b * DM + d] =
        0.25f * (src[d] + src[DM + d] + src[2*DM + d] + src[3*DM + d]);
    if (d == 0) {
        int mode;
        if (cnt[0] >= 4)      mode = 3;
        else if (cnt[1] >= 4) mode = 0;
        else if (cnt[2] > 0)  mode = 2;
        else                  mode = 1;
        float m = mask_at(M, 4*b+0, mode) + mask_at(M, 4*b+1, mode)
                + mask_at(M, 4*b+2, mode) + mask_at(M, 4*b+3, mode);
        mout[b] = (m > 0.0f) ? 1.0f : 0.0f;
    }
}

// ---------------- fused launch 1: masked-sum partials + cp.async proj GEMM --------
__global__ __launch_bounds__(256) void k_fuse1(const float* __restrict__ Wkp,
                                               const float* __restrict__ Wqd) {
    extern __shared__ float dsm[];
    int tid = threadIdx.x;

    if (blockIdx.x < 512) {
        int s = blockIdx.x;
        int n = s & 15, ent = (s >> 4) & 1, seg = s >> 5;
        int d = tid;
        const float* X = ent ? g_dg : g_pg;
        const float* m = ent ? g_md : g_mp;
        int G = ent ? GD : GP;
        int chunk = G / SEG;
        int g0 = seg * chunk;
        float a0 = 0.f, a1 = 0.f, a2 = 0.f, a3 = 0.f;
        for (int g = g0; g < g0 + chunk; g += 4) {
            a0 += m[n*G+g+0] * X[((size_t)(n*G+g+0))*DM + d];
            a1 += m[n*G+g+1] * X[((size_t)(n*G+g+1))*DM + d];
            a2 += m[n*G+g+2] * X[((size_t)(n*G+g+2))*DM + d];
            a3 += m[n*G+g+3] * X[((size_t)(n*G+g+3))*DM + d];
        }
        g_part[((ent*NB + n)*SEG + seg)*DM + d] = (a0 + a1) + (a2 + a3);
        if (d == 0) {
            float c = 0.0f;
            for (int g = g0; g < g0 + chunk; g++) c += m[n*G + g];
            g_cpart[(ent*NB + n)*SEG + seg] = c;
        }
        return;
    }
    int pb = blockIdx.x - 512;
    int bx = pb & 63, by = (pb >> 6) & 1, bz = pb >> 7;
    const float* X; const float* W; float* OUT; int L;
    if (bz == 0) { X = g_pg; W = Wkp; OUT = g_kp; L = GP; }
    else         { if (bx >= 16) return;
                   X = g_dg; W = Wqd; OUT = g_qd; L = GD; }

    float* As = dsm;
    float* Bs = dsm + 2*TILEF;
    uint32_t as_base = smem_u32(As);
    uint32_t bs_base = smem_u32(Bs);

    int lane = tid & 31, w = tid >> 5;
    int g = lane >> 2, tk = lane & 3;
    int wm = (w & 3) * 32, wn = (w >> 2) * 64;
    int m0 = bx * 128, o0 = by * 128;

    int frow[4], fch[4];
    uint32_t aoff[4], boff[4];
#pragma unroll
    for (int s = 0; s < 4; s++) {
        int f = tid + s*256;
        frow[s] = f >> 3; fch[s] = f & 7;
        uint32_t byteoff = (uint32_t)(frow[s]*TSTR + fch[s]*4) * 4u;
        aoff[s] = as_base + byteoff;
        boff[s] = bs_base + byteoff;
    }

    float c[2][8][4];
#pragma unroll
    for (int mi = 0; mi < 2; mi++)
#pragma unroll
        for (int ni = 0; ni < 8; ni++)
#pragma unroll
            for (int r = 0; r < 4; r++) c[mi][ni][r] = 0.0f;

#pragma unroll
    for (int s = 0; s < 4; s++) {
        cp_async16(aoff[s], &X[(size_t)(m0+frow[s])*256 + fch[s]*4]);
        cp_async16(boff[s], &W[(size_t)(o0+frow[s])*256 + fch[s]*4]);
    }
    CP_COMMIT();

    const uint32_t bufbytes = (uint32_t)TILEF * 4u;
    for (int kt = 0; kt < 8; kt++) {
        int buf = kt & 1;
        if (kt < 7) {
            uint32_t nboff = (uint32_t)(buf ^ 1) * bufbytes;
            int k0 = (kt + 1) * 32;
#pragma unroll
            for (int s = 0; s < 4; s++) {
                cp_async16(aoff[s] + nboff, &X[(size_t)(m0+frow[s])*256 + k0 + fch[s]*4]);
                cp_async16(boff[s] + nboff, &W[(size_t)(o0+frow[s])*256 + k0 + fch[s]*4]);
            }
            CP_COMMIT();
            cp_wait<1>();
        } else {
            cp_wait<0>();
        }
        __syncthreads();

        const uint32_t* Ab = (const uint32_t*)(As + buf*TILEF);
        const uint32_t* Bb = (const uint32_t*)(Bs + buf*TILEF);
#pragma unroll
        for (int kh = 0; kh < 4; kh++) {
            int kb = kh*8;
            uint32_t aH[2][4];
#pragma unroll
            for (int mi = 0; mi < 2; mi++) {
                int rb = wm + mi*16 + g;
                aH[mi][0] = Ab[rb*TSTR     + kb+tk  ];
                aH[mi][1] = Ab[(rb+8)*TSTR + kb+tk  ];
                aH[mi][2] = Ab[rb*TSTR     + kb+tk+4];
                aH[mi][3] = Ab[(rb+8)*TSTR + kb+tk+4];
            }
            uint32_t bH[8][2];
#pragma unroll
            for (int ni = 0; ni < 8; ni++) {
                int nb2 = wn + ni*8 + g;
                bH[ni][0] = Bb[nb2*TSTR + kb+tk  ];
                bH[ni][1] = Bb[nb2*TSTR + kb+tk+4];
            }
#pragma unroll
            for (int mi = 0; mi < 2; mi++)
#pragma unroll
                for (int ni = 0; ni < 8; ni++) {
                    float* cc = c[mi][ni];
                    mma_tf32(cc[0],cc[1],cc[2],cc[3],
                             aH[mi][0],aH[mi][1],aH[mi][2],aH[mi][3],
                             bH[ni][0],bH[ni][1]);
                }
        }
        __syncthreads();
    }

#pragma unroll
    for (int mi = 0; mi < 2; mi++)
#pragma unroll
        for (int ni = 0; ni < 8; ni++) {
            int o = o0 + wn + ni*8 + 2*tk;
            int h = o >> 5, dd = o & 31;
            int m = m0 + wm + mi*16 + g;
            int nb = m / L, gg = m % L;
            float* dst = &OUT[(((size_t)(nb*HN + h))*L + gg)*HDM + dd];
            *(float2*)dst = make_float2(c[mi][ni][0], c[mi][ni][1]);
            int m2 = m + 8;
            int nb2 = m2 / L, gg2 = m2 % L;
            float* dst2 = &OUT[(((size_t)(nb2*HN + h))*L + gg2)*HDM + dd];
            *(float2*)dst2 = make_float2(c[mi][ni][2], c[mi][ni][3]);
        }
}

// ---------------- mega kernel: logits (TF32 MMA) + 4x Sinkhorn, E in smem ---------
#define ASTR 137
__global__ __launch_bounds__(512) void k_mega(const float* __restrict__ Wvp,
                                              const float* __restrict__ Wvd,
                                              float* __restrict__ qout, int do_q) {
    extern __shared__ char smem[];
    int tid = threadIdx.x;
    int lane = tid & 31, w = tid >> 5;

    if (blockIdx.x >= NHS) {
        if (!do_q) return;
        float* sp   = (float*)smem;
        float* sd   = sp + DM;
        float* cnts = sd + DM;
        int n = blockIdx.x - NHS;
        if (tid < DM) {
            float accp = 0.0f, accd = 0.0f;
#pragma unroll
            for (int s = 0; s < SEG; s++) {
                accp += g_part[((0*NB + n)*SEG + s)*DM + tid];
                accd += g_part[((1*NB + n)*SEG + s)*DM + tid];
            }
            sp[tid] = accp; sd[tid] = accd;
        }
        if (tid < 2) {
            float c = 0.0f;
#pragma unroll
            for (int s = 0; s < SEG; s++) c += g_cpart[(tid*NB + n)*SEG + s];
            cnts[tid] = c;
        }
        __syncthreads();
        float cp = cnts[0], cd = cnts[1];
        for (int o = w; o < DM; o += 16) {
            float acc = 0.0f;
#pragma unroll
            for (int t = 0; t < 8; t++) {
                int k = lane + t*32;
                acc += sp[k]*Wvp[(size_t)o*DM + k] + sd[k]*Wvd[(size_t)o*DM + k];
            }
#pragma unroll
            for (int off = 16; off > 0; off >>= 1)
                acc += __shfl_xor_sync(0xFFFFFFFFu, acc, off);
            if (lane == 0) {
                qout[(size_t)n*512 + o]       = 0.5f * acc / cp;
                qout[(size_t)n*512 + 256 + o] = 0.5f * acc / cd;
            }
        }
        return;
    }

    int slice = blockIdx.x;
    int n = slice >> 3;
    const float* q = g_qd + (size_t)slice * GD * HDM;
    const float* k = g_kp + (size_t)slice * GP * HDM;

    __half*   Esm   = (__half*)(smem + SM_E);
    uint32_t* Qs    = (uint32_t*)(smem + SM_Q);
    float*    Ksf   = (float*)(smem + SM_K);
    float*    strip = (float*)(smem + SM_Q);     // aliases Qs/Ks after compute
    float*    mrb   = (float*)(smem + SM_MR);
    float*    mcb   = (float*)(smem + SM_MC);
    uint32_t  ks_base = smem_u32(Ksf);

    int g = lane >> 2, tk = lane & 3;
    int wm = (w & 3) * 32, wn = (w >> 2) * 32;

    // K fill coordinates: 2 chunks (16B) per thread per tile
    int krow[2], kch[2];
    uint32_t koff[2];
#pragma unroll
    for (int s = 0; s < 2; s++) {
        int f = tid + s*512;
        krow[s] = f >> 3; kch[s] = f & 7;
        koff[s] = ks_base + (uint32_t)(krow[s]*KSTR2 + kch[s]*4) * 4u;
    }
    // prologue: K tile jt=0 into buffer 0
#pragma unroll
    for (int s = 0; s < 2; s++)
        cp_async16(koff[s], &k[(size_t)krow[s]*HDM + kch[s]*4]);
    CP_COMMIT();

    // Q fill (once, converted RNA)
#pragma unroll
    for (int s = 0; s < 2; s++) {
        int f = tid + s*512;
        int row = f >> 3, c4 = f & 7;
        float4 v = *(const float4*)&q[(size_t)row*HDM + c4*4];
        Qs[(c4*4+0)*ASTR + row] = tf32cvt(v.x);
        Qs[(c4*4+1)*ASTR + row] = tf32cvt(v.y);
        Qs[(c4*4+2)*ASTR + row] = tf32cvt(v.z);
        Qs[(c4*4+3)*ASTR + row] = tf32cvt(v.w);
    }
    if (tid < 128) mrb[tid] = (g_md[n*GD + tid] > 0.0f) ? 0.0f : -10000.0f;
    mcb[tid] = (g_mp[n*GP + tid] > 0.0f) ? 0.0f : -10000.0f;

    const uint32_t kbufbytes = (uint32_t)KBUF * 4u;
    for (int jt = 0; jt < 4; jt++) {
        int j0 = jt * 128;
        int buf = jt & 1;
        if (jt < 3) {
            uint32_t nboff = (uint32_t)(buf ^ 1) * kbufbytes;
#pragma unroll
            for (int s = 0; s < 2; s++)
                cp_async16(koff[s] + nboff,
                           &k[(size_t)(j0 + 128 + krow[s])*HDM + kch[s]*4]);
            CP_COMMIT();
            cp_wait<1>();
        } else {
            cp_wait<0>();
        }
        __syncthreads();

        const uint32_t* Kb = (const uint32_t*)(Ksf + buf*KBUF);

        float c[2][4][4];
#pragma unroll
        for (int mi = 0; mi < 2; mi++)
#pragma unroll
            for (int ni = 0; ni < 4; ni++)
#pragma unroll
                for (int r = 0; r < 4; r++) c[mi][ni][r] = 0.0f;

#pragma unroll
        for (int kh = 0; kh < 4; kh++) {
            int kb = kh*8;
            uint32_t aH[2][4];
#pragma unroll
            for (int mi = 0; mi < 2; mi++) {
                int rb = wm + mi*16 + g;
                aH[mi][0] = Qs[(kb+tk  )*ASTR + rb];
                aH[mi][1] = Qs[(kb+tk  )*ASTR + rb + 8];
                aH[mi][2] = Qs[(kb+tk+4)*ASTR + rb];
                aH[mi][3] = Qs[(kb+tk+4)*ASTR + rb + 8];
            }
            uint32_t bH[4][2];
#pragma unroll
            for (int ni = 0; ni < 4; ni++) {
                int nb = wn + ni*8 + g;
                bH[ni][0] = Kb[nb*KSTR2 + kb+tk  ];
                bH[ni][1] = Kb[nb*KSTR2 + kb+tk+4];
            }
#pragma unroll
            for (int mi = 0; mi < 2; mi++)
#pragma unroll
                for (int ni = 0; ni < 4; ni++) {
                    float* cc = c[mi][ni];
                    mma_tf32(cc[0],cc[1],cc[2],cc[3],
                             aH[mi][0],aH[mi][1],aH[mi][2],aH[mi][3],
                             bH[ni][0],bH[ni][1]);
                }
        }

#pragma unroll
        for (int mi = 0; mi < 2; mi++) {
            int row1 = wm + mi*16 + g;
            int row2 = row1 + 8;
            float br1 = mrb[row1], br2 = mrb[row2];
#pragma unroll
            for (int ni = 0; ni < 4; ni++) {
                int o  = wn + ni*8 + 2*tk;
                int oc = j0 + o;
                float bc0 = mcb[oc], bc1 = mcb[oc+1];
                float* cc = c[mi][ni];
                __half2 xa = __floats2half2_rn(fmaf(cc[0], EXPSC, br1 + bc0),
                                               fmaf(cc[1], EXPSC, br1 + bc1));
                *(uint32_t*)&Esm[row1*ESTR + oc] = ex2_f16x2(*(uint32_t*)&xa);
                __half2 xb = __floats2half2_rn(fmaf(cc[2], EXPSC, br2 + bc0),
                                               fmaf(cc[3], EXPSC, br2 + bc1));
                *(uint32_t*)&Esm[row2*ESTR + oc] = ex2_f16x2(*(uint32_t*)&xb);
            }
        }
        __syncthreads();
    }

    unsigned long long cv2[8];
#pragma unroll
    for (int v = 0; v < 8; v++) cv2[v] = pack2(1.0f);

    for (int iter = 0; iter < 4; iter++) {
        unsigned long long colacc2[8];
#pragma unroll
        for (int v = 0; v < 8; v++) colacc2[v] = 0ULL;

#pragma unroll
        for (int ridx = 0; ridx < 8; ridx++) {
            int i = w + ridx*16;
            const uint4* rp = (const uint4*)(Esm + (size_t)i * ESTR);
            uint4 raws[2];
            unsigned long long ev2[8];
#pragma unroll
            for (int ch = 0; ch < 2; ch++) {
                uint4 raw = rp[ch*32 + lane];
                raws[ch] = raw;
                float2 f0 = __half22float2(*(__half2*)&raw.x);
                float2 f1 = __half22float2(*(__half2*)&raw.y);
                float2 f2 = __half22float2(*(__half2*)&raw.z);
                float2 f3 = __half22float2(*(__half2*)&raw.w);
                ev2[ch*4+0] = packf2(f0.x, f0.y);
                ev2[ch*4+1] = packf2(f1.x, f1.y);
                ev2[ch*4+2] = packf2(f2.x, f2.y);
                ev2[ch*4+3] = packf2(f3.x, f3.y);
            }
            unsigned long long spk = 0ULL;
#pragma unroll
            for (int v = 0; v < 8; v++) fma2(spk, ev2[v], cv2[v]);
            float2 sp2 = unpack2(spk);
            float s = sp2.x + sp2.y;
#pragma unroll
            for (int off = 16; off > 0; off >>= 1)
                s += __shfl_xor_sync(0xFFFFFFFFu, s, off);
            float r = (s > 0.0f) ? 1.0f/s : 0.0f;
            if (iter == 3) {
                if (lane == 0) g_r[slice*GD + i] = r;
                uint4* gp = (uint4*)(g_E + (size_t)slice*GD*GP + (size_t)i*GP);
                gp[lane]      = raws[0];
                gp[32 + lane] = raws[1];
            }
            unsigned long long r2 = pack2(r);
#pragma unroll
            for (int v = 0; v < 8; v++) fma2(colacc2[v], r2, ev2[v]);
        }
#pragma unroll
        for (int v = 0; v < 8; v++) {
            int c0 = (v >> 2)*256 + lane*8 + (v & 3)*2;
            float2 ca = unpack2(colacc2[v]);
            strip[w*544 + SIDX(c0)]   = ca.x;
            strip[w*544 + SIDX(c0+1)] = ca.y;
        }
        __syncthreads();
        {
            int cc = tid;
            float s2 = 0.0f;
#pragma unroll
            for (int ww = 0; ww < 16; ww++) s2 += strip[ww*544 + SIDX(cc)];
            float rec = (s2 > 0.0f) ? 1.0f/s2 : 0.0f;
            if (iter == 3) g_c[slice*GP + cc] = rec;
            else           strip[SIDX(cc)] = rec;
        }
        __syncthreads();
        if (iter < 3) {
#pragma unroll
            for (int v = 0; v < 8; v++) {
                int c0 = (v >> 2)*256 + lane*8 + (v & 3)*2;
                cv2[v] = packf2(strip[SIDX(c0)], strip[SIDX(c0+1)]);
            }
            __syncthreads();
        }
    }
}

// ---------------- write a_dp = diag(r) E diag(c): c folded at staging -------------
#define CSTR 516
__global__ __launch_bounds__(256) void k_adp(float* __restrict__ out) {
    __shared__ float shEC[8*CSTR];      // E*c products
    __shared__ float rsh[8];
    int b = blockIdx.x;
    int n = b >> 7, i = b & 127;
    int tid = threadIdx.x;

    if (tid < 8) rsh[tid] = g_r[(n*8 + tid)*GD + i];
#pragma unroll
    for (int t = 0; t < 2; t++) {
        int f = t*256 + tid;
        int h = f >> 6, qq = f & 63;
        uint4 raw = ((const uint4*)(g_E + ((size_t)(n*8 + h)*GD + i)*GP))[qq];
        const float4* cp4 = (const float4*)(g_c + (size_t)(n*8 + h)*GP);
        float4 c0 = cp4[qq*2];
        float4 c1 = cp4[qq*2 + 1];
        float2 f0 = __half22float2(*(__half2*)&raw.x);
        float2 f1 = __half22float2(*(__half2*)&raw.y);
        float2 f2 = __half22float2(*(__half2*)&raw.z);
        float2 f3 = __half22float2(*(__half2*)&raw.w);
        float* dstE = &shEC[h*CSTR + qq*8];
        ((float4*)dstE)[0] = make_float4(f0.x*c0.x, f0.y*c0.y, f1.x*c0.z, f1.y*c0.w);
        ((float4*)dstE)[1] = make_float4(f2.x*c1.x, f2.y*c1.y, f3.x*c1.z, f3.y*c1.w);
    }
    __syncthreads();

    float* dst = out + (size_t)b * GP * 8;
#pragma unroll
    for (int t = 0; t < 4; t++) {
        int o = t*1024 + tid*4;
        int j = o >> 3, h0 = o & 7;     // h0 in {0,4}
        float4 v;
        v.x = rsh[h0+0] * shEC[(h0+0)*CSTR + j];
        v.y = rsh[h0+1] * shEC[(h0+1)*CSTR + j];
        v.z = rsh[h0+2] * shEC[(h0+2)*CSTR + j];
        v.w = rsh[h0+3] * shEC[(h0+3)*CSTR + j];
        *(float4*)&dst[o] = v;
    }
}

// ---------------- launch -----------------------------------------------------------
extern "C" void kernel_launch(void* const* d_in, const int* in_sizes, int n_in,
                              void* d_out, int out_size) {
    const float* protein = (const float*)d_in[0];
    const float* drug    = (const float*)d_in[1];
    const void*  maskp   = d_in[2];
    const void*  maskd   = d_in[3];
    const float* Wk_p    = (const float*)d_in[5];
    const float* Wv_p    = (const float*)d_in[6];
    const float* Wq_d    = (const float*)d_in[7];
    const float* Wv_d    = (const float*)d_in[9];
    float* out = (float*)d_out;

    size_t adp_elems = (size_t)NB * GD * GP * HN;
    int  write_q   = (((size_t)out_size > adp_elems) || ((size_t)out_size < adp_elems)) ? 1 : 0;
    bool write_adp = ((size_t)out_size >= adp_elems);
    size_t adp_off = ((size_t)out_size >= adp_elems + NB*512) ? (size_t)NB*512 : 0;

    static int smem_set = 0;
    if (!smem_set) {
        cudaFuncSetAttribute(k_mega,  cudaFuncAttributeMaxDynamicSharedMemorySize, SM_TOT);
        cudaFuncSetAttribute(k_fuse1, cudaFuncAttributeMaxDynamicSharedMemorySize, FS_TOT);
        smem_set = 1;
    }

    k_group2<<<NB*GP + NB*GD, 256>>>(protein, drug, maskp, maskd);
    k_fuse1<<<768, 256, FS_TOT>>>(Wk_p, Wq_d);
    k_mega<<<NHS + NB, 512, SM_TOT>>>(Wv_p, Wv_d, out, write_q);
    if (write_adp) {
        k_adp<<<NB*GD, 256>>>(out + adp_off);
    }
}